// round 9
// baseline (speedup 1.0000x reference)
#include <cuda_runtime.h>
#include <cuda_fp16.h>
#include <cstdint>
#include <math.h>

// Problem constants
#define BB 2
#define SS 2048
#define DD 1024
#define HH 16
#define HD 64
#define BH (BB*HH)          // 32
#define MROWS (BB*SS)       // 4096
#define LOG2E 1.4426950408889634f

// ---------------------------------------------------------------------------
// Scratch (static device globals: allocation-free)
// ---------------------------------------------------------------------------
__device__ __half g_qh[BH*SS*HD];     // Q split hi (exp2-domain scaled)
__device__ __half g_ql[BH*SS*HD];     // Q split lo
__device__ __half g_k16[BH*SS*HD];    // K single fp16
__device__ __half g_v16[BH*SS*HD];    // V single fp16
__device__ __half g_xh [MROWS*DD];    // X split hi
__device__ __half g_xl [MROWS*DD];    // X split lo
__device__ __half g_w1t[3*DD*DD];     // W1^T single fp16 [3072,1024]
__device__ __half g_w2t[DD*DD];       // W2^T single fp16 [1024,1024]
__device__ __half g_ah [MROWS*DD];    // attn out split hi
__device__ __half g_al [MROWS*DD];    // attn out split lo

// ---------------------------------------------------------------------------
// PTX helpers (sm_80-portable: mma.sync / ldmatrix / cp.async)
// ---------------------------------------------------------------------------
__device__ __forceinline__ uint32_t smem_to_u32(const void* p) {
    uint32_t a;
    asm("{ .reg .u64 t; cvta.to.shared.u64 t, %1; cvt.u32.u64 %0, t; }"
        : "=r"(a) : "l"(p));
    return a;
}
__device__ __forceinline__ void ldsm_x4(uint32_t* r, uint32_t addr) {
    asm volatile("ldmatrix.sync.aligned.m8n8.x4.shared.b16 {%0,%1,%2,%3}, [%4];"
                 : "=r"(r[0]), "=r"(r[1]), "=r"(r[2]), "=r"(r[3]) : "r"(addr));
}
__device__ __forceinline__ void ldsm_x4_t(uint32_t* r, uint32_t addr) {
    asm volatile("ldmatrix.sync.aligned.m8n8.x4.trans.shared.b16 {%0,%1,%2,%3}, [%4];"
                 : "=r"(r[0]), "=r"(r[1]), "=r"(r[2]), "=r"(r[3]) : "r"(addr));
}
__device__ __forceinline__ void mma_f16(float* c, const uint32_t* a, uint32_t b0, uint32_t b1) {
    asm volatile(
        "mma.sync.aligned.m16n8k16.row.col.f32.f16.f16.f32 "
        "{%0,%1,%2,%3}, {%4,%5,%6,%7}, {%8,%9}, {%0,%1,%2,%3};"
        : "+f"(c[0]), "+f"(c[1]), "+f"(c[2]), "+f"(c[3])
        : "r"(a[0]), "r"(a[1]), "r"(a[2]), "r"(a[3]), "r"(b0), "r"(b1));
}
__device__ __forceinline__ void cp_async16(uint32_t saddr, const void* gptr) {
    asm volatile("cp.async.cg.shared.global [%0], [%1], 16;" :: "r"(saddr), "l"(gptr));
}
#define CP_COMMIT()  asm volatile("cp.async.commit_group;" ::: "memory")
#define CP_WAIT(n)   asm volatile("cp.async.wait_group %0;" :: "n"(n) : "memory")

// XOR swizzle inside 128B rows: element chunk c (16B) of row r
#define SWZ(r, c) ((uint32_t)(r)*128u + ((((uint32_t)(c)) ^ ((uint32_t)(r) & 7u)) << 4))

// Fast exp2 on FMA pipe. t <= 0 expected.
__device__ __forceinline__ float fexp2(float t) {
    t = fmaxf(t, -126.0f);
    float kf = rintf(t);
    float f = t - kf;
    float p = 0.0013333558f;
    p = fmaf(p, f, 0.0096181291f);
    p = fmaf(p, f, 0.0555041087f);
    p = fmaf(p, f, 0.2402265069f);
    p = fmaf(p, f, 0.6931471806f);
    p = fmaf(p, f, 1.0f);
    return __int_as_float(__float_as_int(p) + (((int)kf) << 23));
}
__device__ __forceinline__ uint32_t pack_f16(__half a, __half b) {
    return ((uint32_t)__half_as_ushort(b) << 16) | (uint32_t)__half_as_ushort(a);
}

// ---------------------------------------------------------------------------
// Conversion kernels
// ---------------------------------------------------------------------------
__global__ __launch_bounds__(256)
void split_kernel(const float* __restrict__ x, __half* __restrict__ xh,
                  __half* __restrict__ xl)
{
    int i = (blockIdx.x * 256 + threadIdx.x) * 4;
    float4 v = *reinterpret_cast<const float4*>(x + i);
    float a[4] = {v.x, v.y, v.z, v.w};
    #pragma unroll
    for (int j = 0; j < 4; j++) {
        __half h = __float2half_rn(a[j]);
        xh[i + j] = h;
        xl[i + j] = __float2half_rn(a[j] - __half2float(h));
    }
}

// W[K,N] fp32 -> WT single fp16 [N,K]
__global__ __launch_bounds__(256)
void tconv_kernel(const float* __restrict__ W, __half* __restrict__ WT, int K, int N)
{
    __shared__ float t[32][33];
    const int k0 = blockIdx.y * 32, n0 = blockIdx.x * 32;
    const int tx = threadIdx.x & 31, ty = threadIdx.x >> 5;
    #pragma unroll
    for (int i = 0; i < 4; i++)
        t[ty + i * 8][tx] = W[(size_t)(k0 + ty + i * 8) * N + n0 + tx];
    __syncthreads();
    #pragma unroll
    for (int i = 0; i < 4; i++) {
        int n = ty + i * 8;
        WT[(size_t)(n0 + n) * K + k0 + tx] = __float2half_rn(t[tx][n]);
    }
}

// ---------------------------------------------------------------------------
// mma.sync GEMM: D = (Ah+Al)[M,K] @ B[N,K]^T + bias (A fp16-split, B single).
// BM=128, BN=256, BK=32. 8 warps in 2x4 grid, warp tile 64x64 (MMA-bound:
// smem traffic 128KB/chunk < HMMA 2048 cyc/SMSP). cp.async double buffer.
// EPI=0: Q->split fp16 (scaled), K/V->single fp16, head-major. EPI=1: fp32 C.
// ---------------------------------------------------------------------------
#define TILE_A  10240           // 128 rows * 80B
#define TILE_BB 20480           // 256 rows * 80B
#define STAGE_B 40960           // Ah + Al + B

template<int EPI>
__global__ __launch_bounds__(256, 1)
void mma_gemm(const __half* __restrict__ Ah, const __half* __restrict__ Al,
              const __half* __restrict__ Bs,
              const float* __restrict__ bias, float* __restrict__ C,
              int N, int K)
{
    extern __shared__ char dsm[];
    const uint32_t sb = smem_to_u32(dsm);

    const int tid = threadIdx.x;
    const int wid = tid >> 5;
    const int lane = tid & 31;
    const int bm = blockIdx.y;
    const int bn = blockIdx.x;
    const int wm = wid & 1;       // 0..1 -> 64 M rows
    const int wn = wid >> 1;      // 0..3 -> 64 N cols

    const __half* gA_h = Ah + (size_t)bm * 128 * K;
    const __half* gA_l = Al + (size_t)bm * 128 * K;
    const __half* gB   = Bs + (size_t)bn * 256 * K;

    const int l_row0 = tid >> 2;          // 0..63
    const int l_c16  = tid & 3;

    auto load_stage = [&](int stage, int k0) {
        uint32_t sdst = sb + stage * STAGE_B;
        #pragma unroll
        for (int h = 0; h < 2; h++) {
            int row = l_row0 + h * 64;
            cp_async16(sdst + 0 * TILE_A + row * 80 + l_c16 * 16,
                       gA_h + (size_t)row * K + k0 + l_c16 * 8);
            cp_async16(sdst + 1 * TILE_A + row * 80 + l_c16 * 16,
                       gA_l + (size_t)row * K + k0 + l_c16 * 8);
        }
        #pragma unroll
        for (int h = 0; h < 4; h++) {
            int row = l_row0 + h * 64;
            cp_async16(sdst + 2 * TILE_A + row * 80 + l_c16 * 16,
                       gB + (size_t)row * K + k0 + l_c16 * 8);
        }
    };

    float acc[4][8][4];
    #pragma unroll
    for (int mt = 0; mt < 4; mt++)
        #pragma unroll
        for (int nt = 0; nt < 8; nt++)
            #pragma unroll
            for (int r = 0; r < 4; r++) acc[mt][nt][r] = 0.0f;

    const int NCH = K >> 5;

    load_stage(0, 0);
    CP_COMMIT();

    const uint32_t a_off = (uint32_t)(wm * 64 + (lane & 15)) * 80 + (uint32_t)(lane >> 4) * 16;
    const int bg = lane >> 3;
    const uint32_t b_off = (uint32_t)(wn * 64 + (lane & 7) + ((bg >> 1) << 3)) * 80
                         + (uint32_t)(bg & 1) * 16;

    for (int c = 0; c < NCH; c++) {
        const int stage = c & 1;
        if (c + 1 < NCH) {
            load_stage((c + 1) & 1, (c + 1) * 32);
            CP_COMMIT();
            CP_WAIT(1);
        } else {
            CP_WAIT(0);
        }
        __syncthreads();

        const uint32_t sA_h = sb + stage * STAGE_B + 0 * TILE_A;
        const uint32_t sA_l = sb + stage * STAGE_B + 1 * TILE_A;
        const uint32_t sB   = sb + stage * STAGE_B + 2 * TILE_A;

        #pragma unroll
        for (int ks = 0; ks < 2; ks++) {
            const uint32_t kbyte = ks * 32;
            uint32_t bf[4][4];
            #pragma unroll
            for (int nt2 = 0; nt2 < 4; nt2++)
                ldsm_x4(bf[nt2], sB + b_off + (uint32_t)nt2 * 16 * 80 + kbyte);
            #pragma unroll
            for (int mt = 0; mt < 4; mt++) {
                uint32_t ahf[4], alf[4];
                uint32_t roff = a_off + (uint32_t)mt * 16 * 80 + kbyte;
                ldsm_x4(ahf, sA_h + roff);
                ldsm_x4(alf, sA_l + roff);
                #pragma unroll
                for (int nt = 0; nt < 8; nt++)
                    mma_f16(acc[mt][nt], ahf, bf[nt >> 1][(nt & 1) * 2], bf[nt >> 1][(nt & 1) * 2 + 1]);
                #pragma unroll
                for (int nt = 0; nt < 8; nt++)
                    mma_f16(acc[mt][nt], alf, bf[nt >> 1][(nt & 1) * 2], bf[nt >> 1][(nt & 1) * 2 + 1]);
            }
        }
        __syncthreads();
    }

    #pragma unroll
    for (int mt = 0; mt < 4; mt++) {
        #pragma unroll
        for (int nt = 0; nt < 8; nt++) {
            #pragma unroll
            for (int r = 0; r < 4; r++) {
                int m = bm * 128 + wm * 64 + mt * 16 + (lane >> 2) + (r >> 1) * 8;
                int n = bn * 256 + wn * 64 + nt * 8 + (lane & 3) * 2 + (r & 1);
                float v = acc[mt][nt][r] + __ldg(&bias[n]);
                if (EPI == 0) {
                    int part = n >> 10;
                    int b = m >> 11;
                    int s = m & 2047;
                    int col = n & 1023;
                    int hh = col >> 6;
                    int d = col & 63;
                    size_t idx = (((size_t)(b * 16 + hh) * 2048) + s) * 64 + d;
                    if (part == 0) {
                        v *= 0.125f * LOG2E;      // scale + exp2-domain fold
                        __half hi = __float2half_rn(v);
                        g_qh[idx] = hi;
                        g_ql[idx] = __float2half_rn(v - __half2float(hi));
                    } else if (part == 1) {
                        g_k16[idx] = __float2half_rn(v);
                    } else {
                        g_v16[idx] = __float2half_rn(v);
                    }
                } else {
                    C[(size_t)m * N + n] = v;
                }
            }
        }
    }
}

// ---------------------------------------------------------------------------
// Tensor-core flash attention (unchanged from R8): Q fp16-split x K single;
// P fp16-split x V single. Bq=128, Bk=64, 8 warps (warp = 16 q-rows).
// ---------------------------------------------------------------------------
__global__ __launch_bounds__(256, 1)
void flash_mma()
{
    extern __shared__ char fsm[];
    const uint32_t sb = smem_to_u32(fsm);
    const uint32_t sQh = sb, sQl = sb + 16384;

    const int tid = threadIdx.x;
    const int lane = tid & 31;
    const int wid = tid >> 5;
    const int qt = 15 - blockIdx.x;       // heavy tiles first
    const int bh = blockIdx.y;

    const size_t qoff = ((size_t)bh * SS + qt * 128) * HD;

    auto load_Q = [&]() {
        #pragma unroll
        for (int i = 0; i < 4; i++) {
            int ch = tid + i * 256;
            int r = ch >> 3, c = ch & 7;
            cp_async16(sQh + SWZ(r, c), g_qh + qoff + (size_t)r * 64 + c * 8);
            cp_async16(sQl + SWZ(r, c), g_ql + qoff + (size_t)r * 64 + c * 8);
        }
    };
    auto load_KV = [&](int stage, int kt) {
        uint32_t sbase = sb + 32768 + stage * 16384;
        size_t off = ((size_t)bh * SS + kt * 64) * HD;
        const __half* srcs[2] = { g_k16 + off, g_v16 + off };
        #pragma unroll
        for (int b = 0; b < 2; b++)
            #pragma unroll
            for (int i = 0; i < 2; i++) {
                int ch = tid + i * 256;
                int r = ch >> 3, c = ch & 7;
                cp_async16(sbase + b * 8192 + SWZ(r, c), srcs[b] + (size_t)r * 64 + c * 8);
            }
    };

    const int nkt = 2 * qt + 2;

    load_Q();
    load_KV(0, 0);
    CP_COMMIT();

    uint32_t qh[4][4], ql[4][4];
    float oacc[8][4];
    #pragma unroll
    for (int nt = 0; nt < 8; nt++)
        #pragma unroll
        for (int j = 0; j < 4; j++) oacc[nt][j] = 0.0f;
    float m_s[2] = {-1e30f, -1e30f};
    float l_s[2] = {0.0f, 0.0f};

    for (int kt = 0; kt < nkt; kt++) {
        const int stage = kt & 1;
        if (kt + 1 < nkt) {
            load_KV((kt + 1) & 1, kt + 1);
            CP_COMMIT();
            CP_WAIT(1);
        } else {
            CP_WAIT(0);
        }
        __syncthreads();

        if (kt == 0) {
            #pragma unroll
            for (int t = 0; t < 4; t++) {
                int row = wid * 16 + (lane & 15);
                int c = t * 2 + (lane >> 4);
                ldsm_x4(qh[t], sQh + SWZ(row, c));
                ldsm_x4(ql[t], sQl + SWZ(row, c));
            }
        }

        const uint32_t stK = sb + 32768 + stage * 16384;
        const uint32_t stV = stK + 8192;

        float sacc[8][4];
        #pragma unroll
        for (int nt = 0; nt < 8; nt++)
            #pragma unroll
            for (int j = 0; j < 4; j++) sacc[nt][j] = 0.0f;

        // ---- S = (Qh+Ql) K^T ----
        #pragma unroll
        for (int t = 0; t < 4; t++) {
            uint32_t k4[4][4];
            const int g = lane >> 3;
            #pragma unroll
            for (int p = 0; p < 4; p++) {
                int row = p * 16 + (lane & 7) + ((g >> 1) << 3);
                int c = t * 2 + (g & 1);
                ldsm_x4(k4[p], stK + SWZ(row, c));
            }
            #pragma unroll
            for (int p = 0; p < 4; p++) {
                mma_f16(sacc[2*p],   qh[t], k4[p][0], k4[p][1]);
                mma_f16(sacc[2*p+1], qh[t], k4[p][2], k4[p][3]);
            }
            #pragma unroll
            for (int p = 0; p < 4; p++) {
                mma_f16(sacc[2*p],   ql[t], k4[p][0], k4[p][1]);
                mma_f16(sacc[2*p+1], ql[t], k4[p][2], k4[p][3]);
            }
        }

        if (kt >= 2 * qt) {
            int r0 = qt * 128 + wid * 16 + (lane >> 2);
            #pragma unroll
            for (int nt = 0; nt < 8; nt++)
                #pragma unroll
                for (int j = 0; j < 4; j++) {
                    int row = r0 + (j >> 1) * 8;
                    int col = kt * 64 + nt * 8 + (lane & 3) * 2 + (j & 1);
                    if (col > row) sacc[nt][j] = -1e30f;
                }
        }

        float rmax[2] = {-1e30f, -1e30f};
        #pragma unroll
        for (int nt = 0; nt < 8; nt++) {
            rmax[0] = fmaxf(rmax[0], fmaxf(sacc[nt][0], sacc[nt][1]));
            rmax[1] = fmaxf(rmax[1], fmaxf(sacc[nt][2], sacc[nt][3]));
        }
        #pragma unroll
        for (int h = 0; h < 2; h++) {
            rmax[h] = fmaxf(rmax[h], __shfl_xor_sync(0xffffffffu, rmax[h], 1));
            rmax[h] = fmaxf(rmax[h], __shfl_xor_sync(0xffffffffu, rmax[h], 2));
        }
        float corr[2];
        #pragma unroll
        for (int h = 0; h < 2; h++) {
            float mnew = fmaxf(m_s[h], rmax[h]);
            corr[h] = fexp2(m_s[h] - mnew);
            m_s[h] = mnew;
        }

        uint32_t phpk[8][2], plpk[8][2];
        float rsum[2] = {0.0f, 0.0f};
        #pragma unroll
        for (int nt = 0; nt < 8; nt++) {
            #pragma unroll
            for (int h = 0; h < 2; h++) {
                float p0 = fexp2(sacc[nt][2*h]   - m_s[h]);
                float p1 = fexp2(sacc[nt][2*h+1] - m_s[h]);
                rsum[h] += p0 + p1;
                __half h0 = __float2half_rn(p0);
                __half h1 = __float2half_rn(p1);
                phpk[nt][h] = pack_f16(h0, h1);
                plpk[nt][h] = pack_f16(
                    __float2half_rn(p0 - __half2float(h0)),
                    __float2half_rn(p1 - __half2float(h1)));
            }
        }
        #pragma unroll
        for (int h = 0; h < 2; h++) {
            rsum[h] += __shfl_xor_sync(0xffffffffu, rsum[h], 1);
            rsum[h] += __shfl_xor_sync(0xffffffffu, rsum[h], 2);
            l_s[h] = l_s[h] * corr[h] + rsum[h];
        }
        #pragma unroll
        for (int nt = 0; nt < 8; nt++) {
            oacc[nt][0] *= corr[0];
            oacc[nt][1] *= corr[0];
            oacc[nt][2] *= corr[1];
            oacc[nt][3] *= corr[1];
        }

        // ---- O += (Ph+Pl) V ----
        #pragma unroll
        for (int t = 0; t < 4; t++) {
            uint32_t pa_h[4] = { phpk[2*t][0], phpk[2*t][1], phpk[2*t+1][0], phpk[2*t+1][1] };
            uint32_t pa_l[4] = { plpk[2*t][0], plpk[2*t][1], plpk[2*t+1][0], plpk[2*t+1][1] };
            uint32_t v4[4][4];
            #pragma unroll
            for (int p = 0; p < 4; p++) {
                int row = t * 16 + (lane & 15);
                int c = 2 * p + (lane >> 4);
                ldsm_x4_t(v4[p], stV + SWZ(row, c));
            }
            #pragma unroll
            for (int p = 0; p < 4; p++) {
                mma_f16(oacc[2*p],   pa_h, v4[p][0], v4[p][1]);
                mma_f16(oacc[2*p+1], pa_h, v4[p][2], v4[p][3]);
            }
            #pragma unroll
            for (int p = 0; p < 4; p++) {
                mma_f16(oacc[2*p],   pa_l, v4[p][0], v4[p][1]);
                mma_f16(oacc[2*p+1], pa_l, v4[p][2], v4[p][3]);
            }
        }
        __syncthreads();
    }

    const int b = bh >> 4;
    const int head = bh & 15;
    float inv[2] = {1.0f / l_s[0], 1.0f / l_s[1]};
    #pragma unroll
    for (int h = 0; h < 2; h++) {
        int srow = qt * 128 + wid * 16 + (lane >> 2) + h * 8;
        size_t base = ((size_t)(b * SS + srow)) * DD + head * 64 + (lane & 3) * 2;
        #pragma unroll
        for (int nt = 0; nt < 8; nt++) {
            float o0 = oacc[nt][2*h]   * inv[h];
            float o1 = oacc[nt][2*h+1] * inv[h];
            __half h0 = __float2half_rn(o0);
            __half h1 = __float2half_rn(o1);
            *reinterpret_cast<uint32_t*>(g_ah + base + nt * 8) = pack_f16(h0, h1);
            *reinterpret_cast<uint32_t*>(g_al + base + nt * 8) = pack_f16(
                __float2half_rn(o0 - __half2float(h0)),
                __float2half_rn(o1 - __half2float(h1)));
        }
    }
}

// ---------------------------------------------------------------------------
extern "C" void kernel_launch(void* const* d_in, const int* in_sizes, int n_in,
                              void* d_out, int out_size)
{
    (void)in_sizes; (void)n_in; (void)out_size;
    const float* x   = (const float*)d_in[0];
    const float* w1  = (const float*)d_in[1];
    const float* b1  = (const float*)d_in[2];
    const float* w2  = (const float*)d_in[3];
    const float* b2  = (const float*)d_in[4];
    float* out = (float*)d_out;

    const int SMEM_DYN = 2 * STAGE_B;          // 81920
    const int SMEM_FL  = 65536;                // 64KB
    cudaFuncSetAttribute(mma_gemm<0>, cudaFuncAttributeMaxDynamicSharedMemorySize, SMEM_DYN);
    cudaFuncSetAttribute(mma_gemm<1>, cudaFuncAttributeMaxDynamicSharedMemorySize, SMEM_DYN);
    cudaFuncSetAttribute(flash_mma, cudaFuncAttributeMaxDynamicSharedMemorySize, SMEM_FL);

    void *p_xh, *p_xl, *p_w1t, *p_w2t, *p_ah, *p_al;
    cudaGetSymbolAddress(&p_xh, g_xh);   cudaGetSymbolAddress(&p_xl, g_xl);
    cudaGetSymbolAddress(&p_w1t, g_w1t); cudaGetSymbolAddress(&p_w2t, g_w2t);
    cudaGetSymbolAddress(&p_ah, g_ah);   cudaGetSymbolAddress(&p_al, g_al);

    split_kernel<<<MROWS * DD / 1024, 256>>>(x, (__half*)p_xh, (__half*)p_xl);
    tconv_kernel<<<dim3(3 * DD / 32, DD / 32), 256>>>(w1, (__half*)p_w1t, DD, 3 * DD);
    tconv_kernel<<<dim3(DD / 32, DD / 32), 256>>>(w2, (__half*)p_w2t, DD, DD);

    mma_gemm<0><<<dim3(3 * DD / 256, MROWS / 128), 256, SMEM_DYN>>>(
        (const __half*)p_xh, (const __half*)p_xl, (const __half*)p_w1t,
        b1, nullptr, 3 * DD, DD);

    flash_mma<<<dim3(SS / 128, BH), 256, SMEM_FL>>>();

    mma_gemm<1><<<dim3(DD / 256, MROWS / 128), 256, SMEM_DYN>>>(
        (const __half*)p_ah, (const __half*)p_al, (const __half*)p_w2t,
        b2, out, DD, DD);
}

// round 10
// speedup vs baseline: 1.1536x; 1.1536x over previous
#include <cuda_runtime.h>
#include <cuda_fp16.h>
#include <cstdint>
#include <math.h>

// Problem constants
#define BB 2
#define SS 2048
#define DD 1024
#define HH 16
#define HD 64
#define BH (BB*HH)          // 32
#define MROWS (BB*SS)       // 4096
#define LOG2E 1.4426950408889634f

// ---------------------------------------------------------------------------
// Scratch (static device globals: allocation-free)
// ---------------------------------------------------------------------------
__device__ __half g_qh[BH*SS*HD];     // Q split hi (exp2-domain scaled)
__device__ __half g_ql[BH*SS*HD];     // Q split lo
__device__ __half g_k16[BH*SS*HD];    // K single fp16
__device__ __half g_v16[BH*SS*HD];    // V single fp16
__device__ __half g_xh [MROWS*DD];    // X split hi
__device__ __half g_xl [MROWS*DD];    // X split lo
__device__ __half g_w1t[3*DD*DD];     // W1^T single fp16 [3072,1024]
__device__ __half g_w2t[DD*DD];       // W2^T single fp16 [1024,1024]
__device__ __half g_ah [MROWS*DD];    // attn out split hi
__device__ __half g_al [MROWS*DD];    // attn out split lo

// ---------------------------------------------------------------------------
// PTX helpers (sm_80-portable: mma.sync / ldmatrix / cp.async)
// ---------------------------------------------------------------------------
__device__ __forceinline__ uint32_t smem_to_u32(const void* p) {
    uint32_t a;
    asm("{ .reg .u64 t; cvta.to.shared.u64 t, %1; cvt.u32.u64 %0, t; }"
        : "=r"(a) : "l"(p));
    return a;
}
__device__ __forceinline__ void ldsm_x4(uint32_t* r, uint32_t addr) {
    asm volatile("ldmatrix.sync.aligned.m8n8.x4.shared.b16 {%0,%1,%2,%3}, [%4];"
                 : "=r"(r[0]), "=r"(r[1]), "=r"(r[2]), "=r"(r[3]) : "r"(addr));
}
__device__ __forceinline__ void ldsm_x4_t(uint32_t* r, uint32_t addr) {
    asm volatile("ldmatrix.sync.aligned.m8n8.x4.trans.shared.b16 {%0,%1,%2,%3}, [%4];"
                 : "=r"(r[0]), "=r"(r[1]), "=r"(r[2]), "=r"(r[3]) : "r"(addr));
}
__device__ __forceinline__ void mma_f16(float* c, const uint32_t* a, uint32_t b0, uint32_t b1) {
    asm volatile(
        "mma.sync.aligned.m16n8k16.row.col.f32.f16.f16.f32 "
        "{%0,%1,%2,%3}, {%4,%5,%6,%7}, {%8,%9}, {%0,%1,%2,%3};"
        : "+f"(c[0]), "+f"(c[1]), "+f"(c[2]), "+f"(c[3])
        : "r"(a[0]), "r"(a[1]), "r"(a[2]), "r"(a[3]), "r"(b0), "r"(b1));
}
__device__ __forceinline__ void cp_async16(uint32_t saddr, const void* gptr) {
    asm volatile("cp.async.cg.shared.global [%0], [%1], 16;" :: "r"(saddr), "l"(gptr));
}
#define CP_COMMIT()  asm volatile("cp.async.commit_group;" ::: "memory")
#define CP_WAIT(n)   asm volatile("cp.async.wait_group %0;" :: "n"(n) : "memory")

// XOR swizzle inside 128B rows: element chunk c (16B) of row r
#define SWZ(r, c) ((uint32_t)(r)*128u + ((((uint32_t)(c)) ^ ((uint32_t)(r) & 7u)) << 4))

// Fast exp2 on FMA pipe. t <= 0 expected.
__device__ __forceinline__ float fexp2(float t) {
    t = fmaxf(t, -126.0f);
    float kf = rintf(t);
    float f = t - kf;
    float p = 0.0013333558f;
    p = fmaf(p, f, 0.0096181291f);
    p = fmaf(p, f, 0.0555041087f);
    p = fmaf(p, f, 0.2402265069f);
    p = fmaf(p, f, 0.6931471806f);
    p = fmaf(p, f, 1.0f);
    return __int_as_float(__float_as_int(p) + (((int)kf) << 23));
}
__device__ __forceinline__ uint32_t pack_f16(__half a, __half b) {
    return ((uint32_t)__half_as_ushort(b) << 16) | (uint32_t)__half_as_ushort(a);
}

// ---------------------------------------------------------------------------
// Conversion kernels
// ---------------------------------------------------------------------------
__global__ __launch_bounds__(256)
void split_kernel(const float* __restrict__ x, __half* __restrict__ xh,
                  __half* __restrict__ xl)
{
    int i = (blockIdx.x * 256 + threadIdx.x) * 4;
    float4 v = *reinterpret_cast<const float4*>(x + i);
    float a[4] = {v.x, v.y, v.z, v.w};
    #pragma unroll
    for (int j = 0; j < 4; j++) {
        __half h = __float2half_rn(a[j]);
        xh[i + j] = h;
        xl[i + j] = __float2half_rn(a[j] - __half2float(h));
    }
}

// W[K,N] fp32 -> WT single fp16 [N,K]
__global__ __launch_bounds__(256)
void tconv_kernel(const float* __restrict__ W, __half* __restrict__ WT, int K, int N)
{
    __shared__ float t[32][33];
    const int k0 = blockIdx.y * 32, n0 = blockIdx.x * 32;
    const int tx = threadIdx.x & 31, ty = threadIdx.x >> 5;
    #pragma unroll
    for (int i = 0; i < 4; i++)
        t[ty + i * 8][tx] = W[(size_t)(k0 + ty + i * 8) * N + n0 + tx];
    __syncthreads();
    #pragma unroll
    for (int i = 0; i < 4; i++) {
        int n = ty + i * 8;
        WT[(size_t)(n0 + n) * K + k0 + tx] = __float2half_rn(t[tx][n]);
    }
}

// ---------------------------------------------------------------------------
// mma.sync GEMM (R8 config): D = (Ah+Al)[M,K] @ B[N,K]^T + bias.
// BM=BN=128, BK=32, 8 warps (2x4), warp tile 64x32, 2 CTAs/SM.
// EPI=0: Q->split fp16 (scaled), K/V->single fp16, head-major. EPI=1: fp32 C.
// ---------------------------------------------------------------------------
#define TILE_B  10240           // 128 rows * 80B
#define STAGE_B 30720           // 3 tiles (Ah, Al, B)

template<int EPI>
__global__ __launch_bounds__(256, 2)
void mma_gemm(const __half* __restrict__ Ah, const __half* __restrict__ Al,
              const __half* __restrict__ Bs,
              const float* __restrict__ bias, float* __restrict__ C,
              int N, int K)
{
    extern __shared__ char dsm[];
    const uint32_t sb = smem_to_u32(dsm);

    const int tid = threadIdx.x;
    const int wid = tid >> 5;
    const int lane = tid & 31;
    const int bm = blockIdx.y;
    const int bn = blockIdx.x;
    const int wm = wid & 1;
    const int wn = wid >> 1;

    const __half* gsrc[3];
    gsrc[0] = Ah + (size_t)bm * 128 * K;
    gsrc[1] = Al + (size_t)bm * 128 * K;
    gsrc[2] = Bs + (size_t)bn * 128 * K;

    const int l_row0 = tid >> 2;
    const int l_c16  = tid & 3;

    auto load_stage = [&](int stage, int k0) {
        uint32_t sdst = sb + stage * STAGE_B;
        #pragma unroll
        for (int op = 0; op < 3; op++) {
            const __half* g = gsrc[op];
            #pragma unroll
            for (int h = 0; h < 2; h++) {
                int row = l_row0 + h * 64;
                cp_async16(sdst + op * TILE_B + row * 80 + l_c16 * 16,
                           g + (size_t)row * K + k0 + l_c16 * 8);
            }
        }
    };

    float acc[4][4][4];
    #pragma unroll
    for (int mt = 0; mt < 4; mt++)
        #pragma unroll
        for (int nt = 0; nt < 4; nt++)
            #pragma unroll
            for (int r = 0; r < 4; r++) acc[mt][nt][r] = 0.0f;

    const int NCH = K >> 5;

    load_stage(0, 0);
    CP_COMMIT();

    const uint32_t a_off = (uint32_t)(wm * 64 + (lane & 15)) * 80 + (uint32_t)(lane >> 4) * 16;
    const int bg = lane >> 3;
    const uint32_t b_off = (uint32_t)(wn * 32 + (lane & 7) + ((bg >> 1) << 3)) * 80
                         + (uint32_t)(bg & 1) * 16;

    for (int c = 0; c < NCH; c++) {
        const int stage = c & 1;
        if (c + 1 < NCH) {
            load_stage((c + 1) & 1, (c + 1) * 32);
            CP_COMMIT();
            CP_WAIT(1);
        } else {
            CP_WAIT(0);
        }
        __syncthreads();

        const uint32_t sA_h = sb + stage * STAGE_B + 0 * TILE_B;
        const uint32_t sA_l = sb + stage * STAGE_B + 1 * TILE_B;
        const uint32_t sB   = sb + stage * STAGE_B + 2 * TILE_B;

        #pragma unroll
        for (int ks = 0; ks < 2; ks++) {
            const uint32_t kbyte = ks * 32;
            uint32_t bf[2][4];
            #pragma unroll
            for (int nt2 = 0; nt2 < 2; nt2++)
                ldsm_x4(bf[nt2], sB + b_off + (uint32_t)nt2 * 16 * 80 + kbyte);
            #pragma unroll
            for (int mt = 0; mt < 4; mt++) {
                uint32_t ahf[4], alf[4];
                uint32_t roff = a_off + (uint32_t)mt * 16 * 80 + kbyte;
                ldsm_x4(ahf, sA_h + roff);
                ldsm_x4(alf, sA_l + roff);
                #pragma unroll
                for (int nt = 0; nt < 4; nt++)
                    mma_f16(acc[mt][nt], ahf, bf[nt >> 1][(nt & 1) * 2], bf[nt >> 1][(nt & 1) * 2 + 1]);
                #pragma unroll
                for (int nt = 0; nt < 4; nt++)
                    mma_f16(acc[mt][nt], alf, bf[nt >> 1][(nt & 1) * 2], bf[nt >> 1][(nt & 1) * 2 + 1]);
            }
        }
        __syncthreads();
    }

    #pragma unroll
    for (int mt = 0; mt < 4; mt++) {
        #pragma unroll
        for (int nt = 0; nt < 4; nt++) {
            #pragma unroll
            for (int r = 0; r < 4; r++) {
                int m = bm * 128 + wm * 64 + mt * 16 + (lane >> 2) + (r >> 1) * 8;
                int n = bn * 128 + wn * 32 + nt * 8 + (lane & 3) * 2 + (r & 1);
                float v = acc[mt][nt][r] + __ldg(&bias[n]);
                if (EPI == 0) {
                    int part = n >> 10;
                    int b = m >> 11;
                    int s = m & 2047;
                    int col = n & 1023;
                    int hh = col >> 6;
                    int d = col & 63;
                    size_t idx = (((size_t)(b * 16 + hh) * 2048) + s) * 64 + d;
                    if (part == 0) {
                        v *= 0.125f * LOG2E;      // scale + exp2-domain fold
                        __half hi = __float2half_rn(v);
                        g_qh[idx] = hi;
                        g_ql[idx] = __float2half_rn(v - __half2float(hi));
                    } else if (part == 1) {
                        g_k16[idx] = __float2half_rn(v);
                    } else {
                        g_v16[idx] = __float2half_rn(v);
                    }
                } else {
                    C[(size_t)m * N + n] = v;
                }
            }
        }
    }
}

// ---------------------------------------------------------------------------
// Tensor-core flash attention: Q fp16-split x K single; P SINGLE fp16 x V single.
// Bq=128, Bk=64, 8 warps (warp = 16 q-rows).
// smem: Qh/Ql 32KB + 2 stages x (K,V) 16KB = 64KB.
// ---------------------------------------------------------------------------
__global__ __launch_bounds__(256, 1)
void flash_mma()
{
    extern __shared__ char fsm[];
    const uint32_t sb = smem_to_u32(fsm);
    const uint32_t sQh = sb, sQl = sb + 16384;

    const int tid = threadIdx.x;
    const int lane = tid & 31;
    const int wid = tid >> 5;
    const int qt = 15 - blockIdx.x;       // heavy tiles first
    const int bh = blockIdx.y;

    const size_t qoff = ((size_t)bh * SS + qt * 128) * HD;

    auto load_Q = [&]() {
        #pragma unroll
        for (int i = 0; i < 4; i++) {
            int ch = tid + i * 256;
            int r = ch >> 3, c = ch & 7;
            cp_async16(sQh + SWZ(r, c), g_qh + qoff + (size_t)r * 64 + c * 8);
            cp_async16(sQl + SWZ(r, c), g_ql + qoff + (size_t)r * 64 + c * 8);
        }
    };
    auto load_KV = [&](int stage, int kt) {
        uint32_t sbase = sb + 32768 + stage * 16384;
        size_t off = ((size_t)bh * SS + kt * 64) * HD;
        const __half* srcs[2] = { g_k16 + off, g_v16 + off };
        #pragma unroll
        for (int b = 0; b < 2; b++)
            #pragma unroll
            for (int i = 0; i < 2; i++) {
                int ch = tid + i * 256;
                int r = ch >> 3, c = ch & 7;
                cp_async16(sbase + b * 8192 + SWZ(r, c), srcs[b] + (size_t)r * 64 + c * 8);
            }
    };

    const int nkt = 2 * qt + 2;

    load_Q();
    load_KV(0, 0);
    CP_COMMIT();

    uint32_t qh[4][4], ql[4][4];
    float oacc[8][4];
    #pragma unroll
    for (int nt = 0; nt < 8; nt++)
        #pragma unroll
        for (int j = 0; j < 4; j++) oacc[nt][j] = 0.0f;
    float m_s[2] = {-1e30f, -1e30f};
    float l_s[2] = {0.0f, 0.0f};

    for (int kt = 0; kt < nkt; kt++) {
        const int stage = kt & 1;
        if (kt + 1 < nkt) {
            load_KV((kt + 1) & 1, kt + 1);
            CP_COMMIT();
            CP_WAIT(1);
        } else {
            CP_WAIT(0);
        }
        __syncthreads();

        if (kt == 0) {
            #pragma unroll
            for (int t = 0; t < 4; t++) {
                int row = wid * 16 + (lane & 15);
                int c = t * 2 + (lane >> 4);
                ldsm_x4(qh[t], sQh + SWZ(row, c));
                ldsm_x4(ql[t], sQl + SWZ(row, c));
            }
        }

        const uint32_t stK = sb + 32768 + stage * 16384;
        const uint32_t stV = stK + 8192;

        float sacc[8][4];
        #pragma unroll
        for (int nt = 0; nt < 8; nt++)
            #pragma unroll
            for (int j = 0; j < 4; j++) sacc[nt][j] = 0.0f;

        // ---- S = (Qh+Ql) K^T ----
        #pragma unroll
        for (int t = 0; t < 4; t++) {
            uint32_t k4[4][4];
            const int g = lane >> 3;
            #pragma unroll
            for (int p = 0; p < 4; p++) {
                int row = p * 16 + (lane & 7) + ((g >> 1) << 3);
                int c = t * 2 + (g & 1);
                ldsm_x4(k4[p], stK + SWZ(row, c));
            }
            #pragma unroll
            for (int p = 0; p < 4; p++) {
                mma_f16(sacc[2*p],   qh[t], k4[p][0], k4[p][1]);
                mma_f16(sacc[2*p+1], qh[t], k4[p][2], k4[p][3]);
            }
            #pragma unroll
            for (int p = 0; p < 4; p++) {
                mma_f16(sacc[2*p],   ql[t], k4[p][0], k4[p][1]);
                mma_f16(sacc[2*p+1], ql[t], k4[p][2], k4[p][3]);
            }
        }

        if (kt >= 2 * qt) {
            int r0 = qt * 128 + wid * 16 + (lane >> 2);
            #pragma unroll
            for (int nt = 0; nt < 8; nt++)
                #pragma unroll
                for (int j = 0; j < 4; j++) {
                    int row = r0 + (j >> 1) * 8;
                    int col = kt * 64 + nt * 8 + (lane & 3) * 2 + (j & 1);
                    if (col > row) sacc[nt][j] = -1e30f;
                }
        }

        float rmax[2] = {-1e30f, -1e30f};
        #pragma unroll
        for (int nt = 0; nt < 8; nt++) {
            rmax[0] = fmaxf(rmax[0], fmaxf(sacc[nt][0], sacc[nt][1]));
            rmax[1] = fmaxf(rmax[1], fmaxf(sacc[nt][2], sacc[nt][3]));
        }
        #pragma unroll
        for (int h = 0; h < 2; h++) {
            rmax[h] = fmaxf(rmax[h], __shfl_xor_sync(0xffffffffu, rmax[h], 1));
            rmax[h] = fmaxf(rmax[h], __shfl_xor_sync(0xffffffffu, rmax[h], 2));
        }
        float corr[2];
        #pragma unroll
        for (int h = 0; h < 2; h++) {
            float mnew = fmaxf(m_s[h], rmax[h]);
            corr[h] = fexp2(m_s[h] - mnew);
            m_s[h] = mnew;
        }

        // P single fp16 (error ~2e-4, within budget) — halves packing work
        uint32_t phpk[8][2];
        float rsum[2] = {0.0f, 0.0f};
        #pragma unroll
        for (int nt = 0; nt < 8; nt++) {
            #pragma unroll
            for (int h = 0; h < 2; h++) {
                float p0 = fexp2(sacc[nt][2*h]   - m_s[h]);
                float p1 = fexp2(sacc[nt][2*h+1] - m_s[h]);
                rsum[h] += p0 + p1;
                __half2 hp = __floats2half2_rn(p0, p1);
                phpk[nt][h] = *reinterpret_cast<uint32_t*>(&hp);
            }
        }
        #pragma unroll
        for (int h = 0; h < 2; h++) {
            rsum[h] += __shfl_xor_sync(0xffffffffu, rsum[h], 1);
            rsum[h] += __shfl_xor_sync(0xffffffffu, rsum[h], 2);
            l_s[h] = l_s[h] * corr[h] + rsum[h];
        }
        #pragma unroll
        for (int nt = 0; nt < 8; nt++) {
            oacc[nt][0] *= corr[0];
            oacc[nt][1] *= corr[0];
            oacc[nt][2] *= corr[1];
            oacc[nt][3] *= corr[1];
        }

        // ---- O += P V (both single fp16) ----
        #pragma unroll
        for (int t = 0; t < 4; t++) {
            uint32_t pa[4] = { phpk[2*t][0], phpk[2*t][1], phpk[2*t+1][0], phpk[2*t+1][1] };
            uint32_t v4[4][4];
            #pragma unroll
            for (int p = 0; p < 4; p++) {
                int row = t * 16 + (lane & 15);
                int c = 2 * p + (lane >> 4);
                ldsm_x4_t(v4[p], stV + SWZ(row, c));
            }
            #pragma unroll
            for (int p = 0; p < 4; p++) {
                mma_f16(oacc[2*p],   pa, v4[p][0], v4[p][1]);
                mma_f16(oacc[2*p+1], pa, v4[p][2], v4[p][3]);
            }
        }
        __syncthreads();
    }

    const int b = bh >> 4;
    const int head = bh & 15;
    float inv[2] = {1.0f / l_s[0], 1.0f / l_s[1]};
    #pragma unroll
    for (int h = 0; h < 2; h++) {
        int srow = qt * 128 + wid * 16 + (lane >> 2) + h * 8;
        size_t base = ((size_t)(b * SS + srow)) * DD + head * 64 + (lane & 3) * 2;
        #pragma unroll
        for (int nt = 0; nt < 8; nt++) {
            float o0 = oacc[nt][2*h]   * inv[h];
            float o1 = oacc[nt][2*h+1] * inv[h];
            __half h0 = __float2half_rn(o0);
            __half h1 = __float2half_rn(o1);
            *reinterpret_cast<uint32_t*>(g_ah + base + nt * 8) = pack_f16(h0, h1);
            *reinterpret_cast<uint32_t*>(g_al + base + nt * 8) = pack_f16(
                __float2half_rn(o0 - __half2float(h0)),
                __float2half_rn(o1 - __half2float(h1)));
        }
    }
}

// ---------------------------------------------------------------------------
extern "C" void kernel_launch(void* const* d_in, const int* in_sizes, int n_in,
                              void* d_out, int out_size)
{
    (void)in_sizes; (void)n_in; (void)out_size;
    const float* x   = (const float*)d_in[0];
    const float* w1  = (const float*)d_in[1];
    const float* b1  = (const float*)d_in[2];
    const float* w2  = (const float*)d_in[3];
    const float* b2  = (const float*)d_in[4];
    float* out = (float*)d_out;

    const int SMEM_DYN = 2 * STAGE_B;          // 61440
    const int SMEM_FL  = 65536;                // 64KB
    cudaFuncSetAttribute(mma_gemm<0>, cudaFuncAttributeMaxDynamicSharedMemorySize, SMEM_DYN);
    cudaFuncSetAttribute(mma_gemm<1>, cudaFuncAttributeMaxDynamicSharedMemorySize, SMEM_DYN);
    cudaFuncSetAttribute(flash_mma, cudaFuncAttributeMaxDynamicSharedMemorySize, SMEM_FL);

    void *p_xh, *p_xl, *p_w1t, *p_w2t, *p_ah, *p_al;
    cudaGetSymbolAddress(&p_xh, g_xh);   cudaGetSymbolAddress(&p_xl, g_xl);
    cudaGetSymbolAddress(&p_w1t, g_w1t); cudaGetSymbolAddress(&p_w2t, g_w2t);
    cudaGetSymbolAddress(&p_ah, g_ah);   cudaGetSymbolAddress(&p_al, g_al);

    split_kernel<<<MROWS * DD / 1024, 256>>>(x, (__half*)p_xh, (__half*)p_xl);
    tconv_kernel<<<dim3(3 * DD / 32, DD / 32), 256>>>(w1, (__half*)p_w1t, DD, 3 * DD);
    tconv_kernel<<<dim3(DD / 32, DD / 32), 256>>>(w2, (__half*)p_w2t, DD, DD);

    mma_gemm<0><<<dim3(3 * DD / 128, MROWS / 128), 256, SMEM_DYN>>>(
        (const __half*)p_xh, (const __half*)p_xl, (const __half*)p_w1t,
        b1, nullptr, 3 * DD, DD);

    flash_mma<<<dim3(SS / 128, BH), 256, SMEM_FL>>>();

    mma_gemm<1><<<dim3(DD / 128, MROWS / 128), 256, SMEM_DYN>>>(
        (const __half*)p_ah, (const __half*)p_al, (const __half*)p_w2t,
        b2, out, DD, DD);
}

// round 11
// speedup vs baseline: 1.3376x; 1.1595x over previous
#include <cuda_runtime.h>
#include <cuda_fp16.h>
#include <cstdint>
#include <math.h>

// Problem constants
#define BB 2
#define SS 2048
#define DD 1024
#define HH 16
#define HD 64
#define BH (BB*HH)          // 32
#define MROWS (BB*SS)       // 4096
#define LOG2E 1.4426950408889634f

// ---------------------------------------------------------------------------
// Scratch (static device globals: allocation-free)
// ---------------------------------------------------------------------------
__device__ __half g_qh[BH*SS*HD];     // Q split hi (exp2-domain scaled)
__device__ __half g_ql[BH*SS*HD];     // Q split lo
__device__ __half g_k16[BH*SS*HD];    // K single fp16
__device__ __half g_v16[BH*SS*HD];    // V single fp16
__device__ __half g_xh [MROWS*DD];    // X split hi
__device__ __half g_xl [MROWS*DD];    // X split lo
__device__ __half g_w1t[3*DD*DD];     // W1^T single fp16 [3072,1024]
__device__ __half g_w2t[DD*DD];       // W2^T single fp16 [1024,1024]
__device__ __half g_ah [MROWS*DD];    // attn out split hi
__device__ __half g_al [MROWS*DD];    // attn out split lo

// ---------------------------------------------------------------------------
// PTX helpers (sm_80-portable: mma.sync / ldmatrix / cp.async)
// ---------------------------------------------------------------------------
__device__ __forceinline__ uint32_t smem_to_u32(const void* p) {
    uint32_t a;
    asm("{ .reg .u64 t; cvta.to.shared.u64 t, %1; cvt.u32.u64 %0, t; }"
        : "=r"(a) : "l"(p));
    return a;
}
__device__ __forceinline__ void ldsm_x4(uint32_t* r, uint32_t addr) {
    asm volatile("ldmatrix.sync.aligned.m8n8.x4.shared.b16 {%0,%1,%2,%3}, [%4];"
                 : "=r"(r[0]), "=r"(r[1]), "=r"(r[2]), "=r"(r[3]) : "r"(addr));
}
__device__ __forceinline__ void ldsm_x4_t(uint32_t* r, uint32_t addr) {
    asm volatile("ldmatrix.sync.aligned.m8n8.x4.trans.shared.b16 {%0,%1,%2,%3}, [%4];"
                 : "=r"(r[0]), "=r"(r[1]), "=r"(r[2]), "=r"(r[3]) : "r"(addr));
}
__device__ __forceinline__ void mma_f16(float* c, const uint32_t* a, uint32_t b0, uint32_t b1) {
    asm volatile(
        "mma.sync.aligned.m16n8k16.row.col.f32.f16.f16.f32 "
        "{%0,%1,%2,%3}, {%4,%5,%6,%7}, {%8,%9}, {%0,%1,%2,%3};"
        : "+f"(c[0]), "+f"(c[1]), "+f"(c[2]), "+f"(c[3])
        : "r"(a[0]), "r"(a[1]), "r"(a[2]), "r"(a[3]), "r"(b0), "r"(b1));
}
__device__ __forceinline__ void cp_async16(uint32_t saddr, const void* gptr) {
    asm volatile("cp.async.cg.shared.global [%0], [%1], 16;" :: "r"(saddr), "l"(gptr));
}
#define CP_COMMIT()  asm volatile("cp.async.commit_group;" ::: "memory")
#define CP_WAIT(n)   asm volatile("cp.async.wait_group %0;" :: "n"(n) : "memory")

// XOR swizzle inside 128B rows: element chunk c (16B) of row r
#define SWZ(r, c) ((uint32_t)(r)*128u + ((((uint32_t)(c)) ^ ((uint32_t)(r) & 7u)) << 4))

// Fast exp2 on FMA pipe. t <= 0 expected.
__device__ __forceinline__ float fexp2(float t) {
    t = fmaxf(t, -126.0f);
    float kf = rintf(t);
    float f = t - kf;
    float p = 0.0013333558f;
    p = fmaf(p, f, 0.0096181291f);
    p = fmaf(p, f, 0.0555041087f);
    p = fmaf(p, f, 0.2402265069f);
    p = fmaf(p, f, 0.6931471806f);
    p = fmaf(p, f, 1.0f);
    return __int_as_float(__float_as_int(p) + (((int)kf) << 23));
}
__device__ __forceinline__ uint32_t pack_f16(__half a, __half b) {
    return ((uint32_t)__half_as_ushort(b) << 16) | (uint32_t)__half_as_ushort(a);
}

// ---------------------------------------------------------------------------
// Conversion kernels
// ---------------------------------------------------------------------------
__global__ __launch_bounds__(256)
void split_kernel(const float* __restrict__ x, __half* __restrict__ xh,
                  __half* __restrict__ xl)
{
    int i = (blockIdx.x * 256 + threadIdx.x) * 4;
    float4 v = *reinterpret_cast<const float4*>(x + i);
    float a[4] = {v.x, v.y, v.z, v.w};
    #pragma unroll
    for (int j = 0; j < 4; j++) {
        __half h = __float2half_rn(a[j]);
        xh[i + j] = h;
        xl[i + j] = __float2half_rn(a[j] - __half2float(h));
    }
}

// W[K,N] fp32 -> WT single fp16 [N,K]
__global__ __launch_bounds__(256)
void tconv_kernel(const float* __restrict__ W, __half* __restrict__ WT, int K, int N)
{
    __shared__ float t[32][33];
    const int k0 = blockIdx.y * 32, n0 = blockIdx.x * 32;
    const int tx = threadIdx.x & 31, ty = threadIdx.x >> 5;
    #pragma unroll
    for (int i = 0; i < 4; i++)
        t[ty + i * 8][tx] = W[(size_t)(k0 + ty + i * 8) * N + n0 + tx];
    __syncthreads();
    #pragma unroll
    for (int i = 0; i < 4; i++) {
        int n = ty + i * 8;
        WT[(size_t)(n0 + n) * K + k0 + tx] = __float2half_rn(t[tx][n]);
    }
}

// ---------------------------------------------------------------------------
// mma.sync GEMM: D = (Ah+Al)[M,K] @ B[N,K]^T + bias.
// BM=BN=128, BK=64 (128B rows, XOR swizzle -> conflict-free ldmatrix).
// 8 warps (2x4), warp tile 64x32, 2 CTAs/SM, cp.async double buffer.
// EPI=0: Q->split fp16 (scaled), K/V->single fp16, head-major. EPI=1: fp32 C.
// ---------------------------------------------------------------------------
#define TILE_B  16384           // 128 rows * 128B
#define STAGE_B 49152           // 3 tiles (Ah, Al, B)

template<int EPI>
__global__ __launch_bounds__(256, 2)
void mma_gemm(const __half* __restrict__ Ah, const __half* __restrict__ Al,
              const __half* __restrict__ Bs,
              const float* __restrict__ bias, float* __restrict__ C,
              int N, int K)
{
    extern __shared__ char dsm[];
    const uint32_t sb = smem_to_u32(dsm);

    const int tid = threadIdx.x;
    const int wid = tid >> 5;
    const int lane = tid & 31;
    const int bm = blockIdx.y;
    const int bn = blockIdx.x;
    const int wm = wid & 1;
    const int wn = wid >> 1;

    const __half* gsrc[3];
    gsrc[0] = Ah + (size_t)bm * 128 * K;
    gsrc[1] = Al + (size_t)bm * 128 * K;
    gsrc[2] = Bs + (size_t)bn * 128 * K;

    // loader: 1024 16B-chunks per tile; thread does 4 per tile
    auto load_stage = [&](int stage, int k0) {
        uint32_t sdst = sb + stage * STAGE_B;
        #pragma unroll
        for (int op = 0; op < 3; op++) {
            const __half* g = gsrc[op];
            #pragma unroll
            for (int i = 0; i < 4; i++) {
                int ch = tid + i * 256;
                int r = ch >> 3, c = ch & 7;
                cp_async16(sdst + op * TILE_B + SWZ(r, c),
                           g + (size_t)r * K + k0 + c * 8);
            }
        }
    };

    float acc[4][4][4];
    #pragma unroll
    for (int mt = 0; mt < 4; mt++)
        #pragma unroll
        for (int nt = 0; nt < 4; nt++)
            #pragma unroll
            for (int r = 0; r < 4; r++) acc[mt][nt][r] = 0.0f;

    const int NCH = K >> 6;    // K/64

    load_stage(0, 0);
    CP_COMMIT();

    const int bg = lane >> 3;

    for (int c = 0; c < NCH; c++) {
        const int stage = c & 1;
        if (c + 1 < NCH) {
            load_stage((c + 1) & 1, (c + 1) * 64);
            CP_COMMIT();
            CP_WAIT(1);
        } else {
            CP_WAIT(0);
        }
        __syncthreads();

        const uint32_t sA_h = sb + stage * STAGE_B + 0 * TILE_B;
        const uint32_t sA_l = sb + stage * STAGE_B + 1 * TILE_B;
        const uint32_t sB   = sb + stage * STAGE_B + 2 * TILE_B;

        #pragma unroll
        for (int ks = 0; ks < 4; ks++) {
            // B fragments: 2 ldsm covering warp's 32 N-cols x k16
            uint32_t bf[2][4];
            #pragma unroll
            for (int nt2 = 0; nt2 < 2; nt2++) {
                int row = wn * 32 + nt2 * 16 + (lane & 7) + ((bg >> 1) << 3);
                ldsm_x4(bf[nt2], sB + SWZ(row, ks * 2 + (bg & 1)));
            }
            #pragma unroll
            for (int mt = 0; mt < 4; mt++) {
                uint32_t ahf[4], alf[4];
                int row = wm * 64 + mt * 16 + (lane & 15);
                int cc = ks * 2 + (lane >> 4);
                ldsm_x4(ahf, sA_h + SWZ(row, cc));
                ldsm_x4(alf, sA_l + SWZ(row, cc));
                #pragma unroll
                for (int nt = 0; nt < 4; nt++)
                    mma_f16(acc[mt][nt], ahf, bf[nt >> 1][(nt & 1) * 2], bf[nt >> 1][(nt & 1) * 2 + 1]);
                #pragma unroll
                for (int nt = 0; nt < 4; nt++)
                    mma_f16(acc[mt][nt], alf, bf[nt >> 1][(nt & 1) * 2], bf[nt >> 1][(nt & 1) * 2 + 1]);
            }
        }
        __syncthreads();
    }

    #pragma unroll
    for (int mt = 0; mt < 4; mt++) {
        #pragma unroll
        for (int nt = 0; nt < 4; nt++) {
            #pragma unroll
            for (int r = 0; r < 4; r++) {
                int m = bm * 128 + wm * 64 + mt * 16 + (lane >> 2) + (r >> 1) * 8;
                int n = bn * 128 + wn * 32 + nt * 8 + (lane & 3) * 2 + (r & 1);
                float v = acc[mt][nt][r] + __ldg(&bias[n]);
                if (EPI == 0) {
                    int part = n >> 10;
                    int b = m >> 11;
                    int s = m & 2047;
                    int col = n & 1023;
                    int hh = col >> 6;
                    int d = col & 63;
                    size_t idx = (((size_t)(b * 16 + hh) * 2048) + s) * 64 + d;
                    if (part == 0) {
                        v *= 0.125f * LOG2E;      // scale + exp2-domain fold
                        __half hi = __float2half_rn(v);
                        g_qh[idx] = hi;
                        g_ql[idx] = __float2half_rn(v - __half2float(hi));
                    } else if (part == 1) {
                        g_k16[idx] = __float2half_rn(v);
                    } else {
                        g_v16[idx] = __float2half_rn(v);
                    }
                } else {
                    C[(size_t)m * N + n] = v;
                }
            }
        }
    }
}

// ---------------------------------------------------------------------------
// Tensor-core flash attention (unchanged from R10): Q fp16-split x K single;
// P single fp16 x V single. Bq=128, Bk=64, 8 warps (warp = 16 q-rows).
// ---------------------------------------------------------------------------
__global__ __launch_bounds__(256, 1)
void flash_mma()
{
    extern __shared__ char fsm[];
    const uint32_t sb = smem_to_u32(fsm);
    const uint32_t sQh = sb, sQl = sb + 16384;

    const int tid = threadIdx.x;
    const int lane = tid & 31;
    const int wid = tid >> 5;
    const int qt = 15 - blockIdx.x;       // heavy tiles first
    const int bh = blockIdx.y;

    const size_t qoff = ((size_t)bh * SS + qt * 128) * HD;

    auto load_Q = [&]() {
        #pragma unroll
        for (int i = 0; i < 4; i++) {
            int ch = tid + i * 256;
            int r = ch >> 3, c = ch & 7;
            cp_async16(sQh + SWZ(r, c), g_qh + qoff + (size_t)r * 64 + c * 8);
            cp_async16(sQl + SWZ(r, c), g_ql + qoff + (size_t)r * 64 + c * 8);
        }
    };
    auto load_KV = [&](int stage, int kt) {
        uint32_t sbase = sb + 32768 + stage * 16384;
        size_t off = ((size_t)bh * SS + kt * 64) * HD;
        const __half* srcs[2] = { g_k16 + off, g_v16 + off };
        #pragma unroll
        for (int b = 0; b < 2; b++)
            #pragma unroll
            for (int i = 0; i < 2; i++) {
                int ch = tid + i * 256;
                int r = ch >> 3, c = ch & 7;
                cp_async16(sbase + b * 8192 + SWZ(r, c), srcs[b] + (size_t)r * 64 + c * 8);
            }
    };

    const int nkt = 2 * qt + 2;

    load_Q();
    load_KV(0, 0);
    CP_COMMIT();

    uint32_t qh[4][4], ql[4][4];
    float oacc[8][4];
    #pragma unroll
    for (int nt = 0; nt < 8; nt++)
        #pragma unroll
        for (int j = 0; j < 4; j++) oacc[nt][j] = 0.0f;
    float m_s[2] = {-1e30f, -1e30f};
    float l_s[2] = {0.0f, 0.0f};

    for (int kt = 0; kt < nkt; kt++) {
        const int stage = kt & 1;
        if (kt + 1 < nkt) {
            load_KV((kt + 1) & 1, kt + 1);
            CP_COMMIT();
            CP_WAIT(1);
        } else {
            CP_WAIT(0);
        }
        __syncthreads();

        if (kt == 0) {
            #pragma unroll
            for (int t = 0; t < 4; t++) {
                int row = wid * 16 + (lane & 15);
                int c = t * 2 + (lane >> 4);
                ldsm_x4(qh[t], sQh + SWZ(row, c));
                ldsm_x4(ql[t], sQl + SWZ(row, c));
            }
        }

        const uint32_t stK = sb + 32768 + stage * 16384;
        const uint32_t stV = stK + 8192;

        float sacc[8][4];
        #pragma unroll
        for (int nt = 0; nt < 8; nt++)
            #pragma unroll
            for (int j = 0; j < 4; j++) sacc[nt][j] = 0.0f;

        // ---- S = (Qh+Ql) K^T ----
        #pragma unroll
        for (int t = 0; t < 4; t++) {
            uint32_t k4[4][4];
            const int g = lane >> 3;
            #pragma unroll
            for (int p = 0; p < 4; p++) {
                int row = p * 16 + (lane & 7) + ((g >> 1) << 3);
                int c = t * 2 + (g & 1);
                ldsm_x4(k4[p], stK + SWZ(row, c));
            }
            #pragma unroll
            for (int p = 0; p < 4; p++) {
                mma_f16(sacc[2*p],   qh[t], k4[p][0], k4[p][1]);
                mma_f16(sacc[2*p+1], qh[t], k4[p][2], k4[p][3]);
            }
            #pragma unroll
            for (int p = 0; p < 4; p++) {
                mma_f16(sacc[2*p],   ql[t], k4[p][0], k4[p][1]);
                mma_f16(sacc[2*p+1], ql[t], k4[p][2], k4[p][3]);
            }
        }

        if (kt >= 2 * qt) {
            int r0 = qt * 128 + wid * 16 + (lane >> 2);
            #pragma unroll
            for (int nt = 0; nt < 8; nt++)
                #pragma unroll
                for (int j = 0; j < 4; j++) {
                    int row = r0 + (j >> 1) * 8;
                    int col = kt * 64 + nt * 8 + (lane & 3) * 2 + (j & 1);
                    if (col > row) sacc[nt][j] = -1e30f;
                }
        }

        float rmax[2] = {-1e30f, -1e30f};
        #pragma unroll
        for (int nt = 0; nt < 8; nt++) {
            rmax[0] = fmaxf(rmax[0], fmaxf(sacc[nt][0], sacc[nt][1]));
            rmax[1] = fmaxf(rmax[1], fmaxf(sacc[nt][2], sacc[nt][3]));
        }
        #pragma unroll
        for (int h = 0; h < 2; h++) {
            rmax[h] = fmaxf(rmax[h], __shfl_xor_sync(0xffffffffu, rmax[h], 1));
            rmax[h] = fmaxf(rmax[h], __shfl_xor_sync(0xffffffffu, rmax[h], 2));
        }
        float corr[2];
        #pragma unroll
        for (int h = 0; h < 2; h++) {
            float mnew = fmaxf(m_s[h], rmax[h]);
            corr[h] = fexp2(m_s[h] - mnew);
            m_s[h] = mnew;
        }

        // P single fp16 — halves packing work
        uint32_t phpk[8][2];
        float rsum[2] = {0.0f, 0.0f};
        #pragma unroll
        for (int nt = 0; nt < 8; nt++) {
            #pragma unroll
            for (int h = 0; h < 2; h++) {
                float p0 = fexp2(sacc[nt][2*h]   - m_s[h]);
                float p1 = fexp2(sacc[nt][2*h+1] - m_s[h]);
                rsum[h] += p0 + p1;
                __half2 hp = __floats2half2_rn(p0, p1);
                phpk[nt][h] = *reinterpret_cast<uint32_t*>(&hp);
            }
        }
        #pragma unroll
        for (int h = 0; h < 2; h++) {
            rsum[h] += __shfl_xor_sync(0xffffffffu, rsum[h], 1);
            rsum[h] += __shfl_xor_sync(0xffffffffu, rsum[h], 2);
            l_s[h] = l_s[h] * corr[h] + rsum[h];
        }
        #pragma unroll
        for (int nt = 0; nt < 8; nt++) {
            oacc[nt][0] *= corr[0];
            oacc[nt][1] *= corr[0];
            oacc[nt][2] *= corr[1];
            oacc[nt][3] *= corr[1];
        }

        // ---- O += P V ----
        #pragma unroll
        for (int t = 0; t < 4; t++) {
            uint32_t pa[4] = { phpk[2*t][0], phpk[2*t][1], phpk[2*t+1][0], phpk[2*t+1][1] };
            uint32_t v4[4][4];
            #pragma unroll
            for (int p = 0; p < 4; p++) {
                int row = t * 16 + (lane & 15);
                int c = 2 * p + (lane >> 4);
                ldsm_x4_t(v4[p], stV + SWZ(row, c));
            }
            #pragma unroll
            for (int p = 0; p < 4; p++) {
                mma_f16(oacc[2*p],   pa, v4[p][0], v4[p][1]);
                mma_f16(oacc[2*p+1], pa, v4[p][2], v4[p][3]);
            }
        }
        __syncthreads();
    }

    const int b = bh >> 4;
    const int head = bh & 15;
    float inv[2] = {1.0f / l_s[0], 1.0f / l_s[1]};
    #pragma unroll
    for (int h = 0; h < 2; h++) {
        int srow = qt * 128 + wid * 16 + (lane >> 2) + h * 8;
        size_t base = ((size_t)(b * SS + srow)) * DD + head * 64 + (lane & 3) * 2;
        #pragma unroll
        for (int nt = 0; nt < 8; nt++) {
            float o0 = oacc[nt][2*h]   * inv[h];
            float o1 = oacc[nt][2*h+1] * inv[h];
            __half h0 = __float2half_rn(o0);
            __half h1 = __float2half_rn(o1);
            *reinterpret_cast<uint32_t*>(g_ah + base + nt * 8) = pack_f16(h0, h1);
            *reinterpret_cast<uint32_t*>(g_al + base + nt * 8) = pack_f16(
                __float2half_rn(o0 - __half2float(h0)),
                __float2half_rn(o1 - __half2float(h1)));
        }
    }
}

// ---------------------------------------------------------------------------
extern "C" void kernel_launch(void* const* d_in, const int* in_sizes, int n_in,
                              void* d_out, int out_size)
{
    (void)in_sizes; (void)n_in; (void)out_size;
    const float* x   = (const float*)d_in[0];
    const float* w1  = (const float*)d_in[1];
    const float* b1  = (const float*)d_in[2];
    const float* w2  = (const float*)d_in[3];
    const float* b2  = (const float*)d_in[4];
    float* out = (float*)d_out;

    const int SMEM_DYN = 2 * STAGE_B;          // 98304
    const int SMEM_FL  = 65536;                // 64KB
    cudaFuncSetAttribute(mma_gemm<0>, cudaFuncAttributeMaxDynamicSharedMemorySize, SMEM_DYN);
    cudaFuncSetAttribute(mma_gemm<1>, cudaFuncAttributeMaxDynamicSharedMemorySize, SMEM_DYN);
    cudaFuncSetAttribute(flash_mma, cudaFuncAttributeMaxDynamicSharedMemorySize, SMEM_FL);

    void *p_xh, *p_xl, *p_w1t, *p_w2t, *p_ah, *p_al;
    cudaGetSymbolAddress(&p_xh, g_xh);   cudaGetSymbolAddress(&p_xl, g_xl);
    cudaGetSymbolAddress(&p_w1t, g_w1t); cudaGetSymbolAddress(&p_w2t, g_w2t);
    cudaGetSymbolAddress(&p_ah, g_ah);   cudaGetSymbolAddress(&p_al, g_al);

    split_kernel<<<MROWS * DD / 1024, 256>>>(x, (__half*)p_xh, (__half*)p_xl);
    tconv_kernel<<<dim3(3 * DD / 32, DD / 32), 256>>>(w1, (__half*)p_w1t, DD, 3 * DD);
    tconv_kernel<<<dim3(DD / 32, DD / 32), 256>>>(w2, (__half*)p_w2t, DD, DD);

    mma_gemm<0><<<dim3(3 * DD / 128, MROWS / 128), 256, SMEM_DYN>>>(
        (const __half*)p_xh, (const __half*)p_xl, (const __half*)p_w1t,
        b1, nullptr, 3 * DD, DD);

    flash_mma<<<dim3(SS / 128, BH), 256, SMEM_FL>>>();

    mma_gemm<1><<<dim3(DD / 128, MROWS / 128), 256, SMEM_DYN>>>(
        (const __half*)p_ah, (const __half*)p_al, (const __half*)p_w2t,
        b2, out, DD, DD);
}

// round 12
// speedup vs baseline: 1.3717x; 1.0254x over previous
#include <cuda_runtime.h>
#include <cuda_fp16.h>
#include <cstdint>
#include <math.h>

// Problem constants
#define BB 2
#define SS 2048
#define DD 1024
#define HH 16
#define HD 64
#define BH (BB*HH)          // 32
#define MROWS (BB*SS)       // 4096
#define LOG2E 1.4426950408889634f

// ---------------------------------------------------------------------------
// Scratch (static device globals: allocation-free)
// ---------------------------------------------------------------------------
__device__ __half g_qh[BH*SS*HD];     // Q split hi (exp2-domain scaled)
__device__ __half g_ql[BH*SS*HD];     // Q split lo
__device__ __half g_k16[BH*SS*HD];    // K single fp16
__device__ __half g_v16[BH*SS*HD];    // V single fp16
__device__ __half g_xh [MROWS*DD];    // X split hi
__device__ __half g_xl [MROWS*DD];    // X split lo
__device__ __half g_w1t[3*DD*DD];     // W1^T single fp16 [3072,1024]
__device__ __half g_w2t[DD*DD];       // W2^T single fp16 [1024,1024]
__device__ __half g_ah [MROWS*DD];    // attn out split hi
__device__ __half g_al [MROWS*DD];    // attn out split lo

// ---------------------------------------------------------------------------
// PTX helpers (sm_80-portable: mma.sync / ldmatrix / cp.async)
// ---------------------------------------------------------------------------
__device__ __forceinline__ uint32_t smem_to_u32(const void* p) {
    uint32_t a;
    asm("{ .reg .u64 t; cvta.to.shared.u64 t, %1; cvt.u32.u64 %0, t; }"
        : "=r"(a) : "l"(p));
    return a;
}
__device__ __forceinline__ void ldsm_x4(uint32_t* r, uint32_t addr) {
    asm volatile("ldmatrix.sync.aligned.m8n8.x4.shared.b16 {%0,%1,%2,%3}, [%4];"
                 : "=r"(r[0]), "=r"(r[1]), "=r"(r[2]), "=r"(r[3]) : "r"(addr));
}
__device__ __forceinline__ void ldsm_x4_t(uint32_t* r, uint32_t addr) {
    asm volatile("ldmatrix.sync.aligned.m8n8.x4.trans.shared.b16 {%0,%1,%2,%3}, [%4];"
                 : "=r"(r[0]), "=r"(r[1]), "=r"(r[2]), "=r"(r[3]) : "r"(addr));
}
__device__ __forceinline__ void mma_f16(float* c, const uint32_t* a, uint32_t b0, uint32_t b1) {
    asm volatile(
        "mma.sync.aligned.m16n8k16.row.col.f32.f16.f16.f32 "
        "{%0,%1,%2,%3}, {%4,%5,%6,%7}, {%8,%9}, {%0,%1,%2,%3};"
        : "+f"(c[0]), "+f"(c[1]), "+f"(c[2]), "+f"(c[3])
        : "r"(a[0]), "r"(a[1]), "r"(a[2]), "r"(a[3]), "r"(b0), "r"(b1));
}
__device__ __forceinline__ void cp_async16(uint32_t saddr, const void* gptr) {
    asm volatile("cp.async.cg.shared.global [%0], [%1], 16;" :: "r"(saddr), "l"(gptr));
}
#define CP_COMMIT()  asm volatile("cp.async.commit_group;" ::: "memory")
#define CP_WAIT(n)   asm volatile("cp.async.wait_group %0;" :: "n"(n) : "memory")

// XOR swizzle inside 128B rows: element chunk c (16B) of row r
#define SWZ(r, c) ((uint32_t)(r)*128u + ((((uint32_t)(c)) ^ ((uint32_t)(r) & 7u)) << 4))

// Fast exp2 on FMA pipe. t <= 0 expected.
__device__ __forceinline__ float fexp2(float t) {
    t = fmaxf(t, -126.0f);
    float kf = rintf(t);
    float f = t - kf;
    float p = 0.0013333558f;
    p = fmaf(p, f, 0.0096181291f);
    p = fmaf(p, f, 0.0555041087f);
    p = fmaf(p, f, 0.2402265069f);
    p = fmaf(p, f, 0.6931471806f);
    p = fmaf(p, f, 1.0f);
    return __int_as_float(__float_as_int(p) + (((int)kf) << 23));
}
__device__ __forceinline__ uint32_t pack_f16(__half a, __half b) {
    return ((uint32_t)__half_as_ushort(b) << 16) | (uint32_t)__half_as_ushort(a);
}

// ---------------------------------------------------------------------------
// Conversion kernels
// ---------------------------------------------------------------------------
__global__ __launch_bounds__(256)
void split_kernel(const float* __restrict__ x, __half* __restrict__ xh,
                  __half* __restrict__ xl)
{
    int i = (blockIdx.x * 256 + threadIdx.x) * 4;
    float4 v = *reinterpret_cast<const float4*>(x + i);
    float a[4] = {v.x, v.y, v.z, v.w};
    #pragma unroll
    for (int j = 0; j < 4; j++) {
        __half h = __float2half_rn(a[j]);
        xh[i + j] = h;
        xl[i + j] = __float2half_rn(a[j] - __half2float(h));
    }
}

// W[K,N] fp32 -> WT single fp16 [N,K]
__global__ __launch_bounds__(256)
void tconv_kernel(const float* __restrict__ W, __half* __restrict__ WT, int K, int N)
{
    __shared__ float t[32][33];
    const int k0 = blockIdx.y * 32, n0 = blockIdx.x * 32;
    const int tx = threadIdx.x & 31, ty = threadIdx.x >> 5;
    #pragma unroll
    for (int i = 0; i < 4; i++)
        t[ty + i * 8][tx] = W[(size_t)(k0 + ty + i * 8) * N + n0 + tx];
    __syncthreads();
    #pragma unroll
    for (int i = 0; i < 4; i++) {
        int n = ty + i * 8;
        WT[(size_t)(n0 + n) * K + k0 + tx] = __float2half_rn(t[tx][n]);
    }
}

// ---------------------------------------------------------------------------
// mma.sync GEMM: D = (Ah+Al)[M,K] @ B[N,K]^T + bias.
// BM=BN=128, BK=64 (128B rows, XOR swizzle -> conflict-free ldmatrix).
// 8 warps (2x4), warp tile 64x32, 2 CTAs/SM, cp.async double buffer.
// Epilogue stores paired (r, r+1) -> one 32-bit (half2) or 64-bit (float2) store.
// ---------------------------------------------------------------------------
#define TILE_B  16384           // 128 rows * 128B
#define STAGE_B 49152           // 3 tiles (Ah, Al, B)

template<int EPI>
__global__ __launch_bounds__(256, 2)
void mma_gemm(const __half* __restrict__ Ah, const __half* __restrict__ Al,
              const __half* __restrict__ Bs,
              const float* __restrict__ bias, float* __restrict__ C,
              int N, int K)
{
    extern __shared__ char dsm[];
    const uint32_t sb = smem_to_u32(dsm);

    const int tid = threadIdx.x;
    const int wid = tid >> 5;
    const int lane = tid & 31;
    const int bm = blockIdx.y;
    const int bn = blockIdx.x;
    const int wm = wid & 1;
    const int wn = wid >> 1;

    const __half* gsrc[3];
    gsrc[0] = Ah + (size_t)bm * 128 * K;
    gsrc[1] = Al + (size_t)bm * 128 * K;
    gsrc[2] = Bs + (size_t)bn * 128 * K;

    // loader: 1024 16B-chunks per tile; thread does 4 per tile
    auto load_stage = [&](int stage, int k0) {
        uint32_t sdst = sb + stage * STAGE_B;
        #pragma unroll
        for (int op = 0; op < 3; op++) {
            const __half* g = gsrc[op];
            #pragma unroll
            for (int i = 0; i < 4; i++) {
                int ch = tid + i * 256;
                int r = ch >> 3, c = ch & 7;
                cp_async16(sdst + op * TILE_B + SWZ(r, c),
                           g + (size_t)r * K + k0 + c * 8);
            }
        }
    };

    float acc[4][4][4];
    #pragma unroll
    for (int mt = 0; mt < 4; mt++)
        #pragma unroll
        for (int nt = 0; nt < 4; nt++)
            #pragma unroll
            for (int r = 0; r < 4; r++) acc[mt][nt][r] = 0.0f;

    const int NCH = K >> 6;    // K/64

    load_stage(0, 0);
    CP_COMMIT();

    const int bg = lane >> 3;

    for (int c = 0; c < NCH; c++) {
        const int stage = c & 1;
        if (c + 1 < NCH) {
            load_stage((c + 1) & 1, (c + 1) * 64);
            CP_COMMIT();
            CP_WAIT(1);
        } else {
            CP_WAIT(0);
        }
        __syncthreads();

        const uint32_t sA_h = sb + stage * STAGE_B + 0 * TILE_B;
        const uint32_t sA_l = sb + stage * STAGE_B + 1 * TILE_B;
        const uint32_t sB   = sb + stage * STAGE_B + 2 * TILE_B;

        #pragma unroll
        for (int ks = 0; ks < 4; ks++) {
            uint32_t bf[2][4];
            #pragma unroll
            for (int nt2 = 0; nt2 < 2; nt2++) {
                int row = wn * 32 + nt2 * 16 + (lane & 7) + ((bg >> 1) << 3);
                ldsm_x4(bf[nt2], sB + SWZ(row, ks * 2 + (bg & 1)));
            }
            #pragma unroll
            for (int mt = 0; mt < 4; mt++) {
                uint32_t ahf[4], alf[4];
                int row = wm * 64 + mt * 16 + (lane & 15);
                int cc = ks * 2 + (lane >> 4);
                ldsm_x4(ahf, sA_h + SWZ(row, cc));
                ldsm_x4(alf, sA_l + SWZ(row, cc));
                #pragma unroll
                for (int nt = 0; nt < 4; nt++)
                    mma_f16(acc[mt][nt], ahf, bf[nt >> 1][(nt & 1) * 2], bf[nt >> 1][(nt & 1) * 2 + 1]);
                #pragma unroll
                for (int nt = 0; nt < 4; nt++)
                    mma_f16(acc[mt][nt], alf, bf[nt >> 1][(nt & 1) * 2], bf[nt >> 1][(nt & 1) * 2 + 1]);
            }
        }
        __syncthreads();
    }

    // Epilogue: pair (r, r+1) = same row, adjacent cols -> wide stores
    #pragma unroll
    for (int mt = 0; mt < 4; mt++) {
        #pragma unroll
        for (int nt = 0; nt < 4; nt++) {
            #pragma unroll
            for (int rp = 0; rp < 2; rp++) {
                int m = bm * 128 + wm * 64 + mt * 16 + (lane >> 2) + rp * 8;
                int n = bn * 128 + wn * 32 + nt * 8 + (lane & 3) * 2;   // even
                float v0 = acc[mt][nt][rp * 2 + 0] + __ldg(&bias[n]);
                float v1 = acc[mt][nt][rp * 2 + 1] + __ldg(&bias[n + 1]);
                if (EPI == 0) {
                    int part = n >> 10;
                    int b = m >> 11;
                    int s = m & 2047;
                    int col = n & 1023;
                    int hh = col >> 6;
                    int d = col & 63;                      // even
                    size_t idx = (((size_t)(b * 16 + hh) * 2048) + s) * 64 + d;
                    if (part == 0) {
                        v0 *= 0.125f * LOG2E;
                        v1 *= 0.125f * LOG2E;
                        __half h0 = __float2half_rn(v0);
                        __half h1 = __float2half_rn(v1);
                        *reinterpret_cast<uint32_t*>(&g_qh[idx]) = pack_f16(h0, h1);
                        *reinterpret_cast<uint32_t*>(&g_ql[idx]) = pack_f16(
                            __float2half_rn(v0 - __half2float(h0)),
                            __float2half_rn(v1 - __half2float(h1)));
                    } else if (part == 1) {
                        __half2 hp = __floats2half2_rn(v0, v1);
                        *reinterpret_cast<__half2*>(&g_k16[idx]) = hp;
                    } else {
                        __half2 hp = __floats2half2_rn(v0, v1);
                        *reinterpret_cast<__half2*>(&g_v16[idx]) = hp;
                    }
                } else {
                    float2 o = make_float2(v0, v1);
                    *reinterpret_cast<float2*>(&C[(size_t)m * N + n]) = o;
                }
            }
        }
    }
}

// ---------------------------------------------------------------------------
// Tensor-core flash attention: Q fp16-split x K single; P single fp16 x V single.
// Bq=128, Bk=64, 8 warps (warp = 16 q-rows). Now 2 CTAs/SM (regs capped 128).
// smem: Qh/Ql 32KB + 2 stages x (K,V) 16KB = 64KB per CTA.
// ---------------------------------------------------------------------------
__global__ __launch_bounds__(256, 2)
void flash_mma()
{
    extern __shared__ char fsm[];
    const uint32_t sb = smem_to_u32(fsm);
    const uint32_t sQh = sb, sQl = sb + 16384;

    const int tid = threadIdx.x;
    const int lane = tid & 31;
    const int wid = tid >> 5;
    const int qt = 15 - blockIdx.x;       // heavy tiles first
    const int bh = blockIdx.y;

    const size_t qoff = ((size_t)bh * SS + qt * 128) * HD;

    auto load_Q = [&]() {
        #pragma unroll
        for (int i = 0; i < 4; i++) {
            int ch = tid + i * 256;
            int r = ch >> 3, c = ch & 7;
            cp_async16(sQh + SWZ(r, c), g_qh + qoff + (size_t)r * 64 + c * 8);
            cp_async16(sQl + SWZ(r, c), g_ql + qoff + (size_t)r * 64 + c * 8);
        }
    };
    auto load_KV = [&](int stage, int kt) {
        uint32_t sbase = sb + 32768 + stage * 16384;
        size_t off = ((size_t)bh * SS + kt * 64) * HD;
        const __half* srcs[2] = { g_k16 + off, g_v16 + off };
        #pragma unroll
        for (int b = 0; b < 2; b++)
            #pragma unroll
            for (int i = 0; i < 2; i++) {
                int ch = tid + i * 256;
                int r = ch >> 3, c = ch & 7;
                cp_async16(sbase + b * 8192 + SWZ(r, c), srcs[b] + (size_t)r * 64 + c * 8);
            }
    };

    const int nkt = 2 * qt + 2;

    load_Q();
    load_KV(0, 0);
    CP_COMMIT();

    uint32_t qh[4][4], ql[4][4];
    float oacc[8][4];
    #pragma unroll
    for (int nt = 0; nt < 8; nt++)
        #pragma unroll
        for (int j = 0; j < 4; j++) oacc[nt][j] = 0.0f;
    float m_s[2] = {-1e30f, -1e30f};
    float l_s[2] = {0.0f, 0.0f};

    for (int kt = 0; kt < nkt; kt++) {
        const int stage = kt & 1;
        if (kt + 1 < nkt) {
            load_KV((kt + 1) & 1, kt + 1);
            CP_COMMIT();
            CP_WAIT(1);
        } else {
            CP_WAIT(0);
        }
        __syncthreads();

        if (kt == 0) {
            #pragma unroll
            for (int t = 0; t < 4; t++) {
                int row = wid * 16 + (lane & 15);
                int c = t * 2 + (lane >> 4);
                ldsm_x4(qh[t], sQh + SWZ(row, c));
                ldsm_x4(ql[t], sQl + SWZ(row, c));
            }
        }

        const uint32_t stK = sb + 32768 + stage * 16384;
        const uint32_t stV = stK + 8192;

        float sacc[8][4];
        #pragma unroll
        for (int nt = 0; nt < 8; nt++)
            #pragma unroll
            for (int j = 0; j < 4; j++) sacc[nt][j] = 0.0f;

        // ---- S = (Qh+Ql) K^T ----
        #pragma unroll
        for (int t = 0; t < 4; t++) {
            uint32_t k4[4][4];
            const int g = lane >> 3;
            #pragma unroll
            for (int p = 0; p < 4; p++) {
                int row = p * 16 + (lane & 7) + ((g >> 1) << 3);
                int c = t * 2 + (g & 1);
                ldsm_x4(k4[p], stK + SWZ(row, c));
            }
            #pragma unroll
            for (int p = 0; p < 4; p++) {
                mma_f16(sacc[2*p],   qh[t], k4[p][0], k4[p][1]);
                mma_f16(sacc[2*p+1], qh[t], k4[p][2], k4[p][3]);
            }
            #pragma unroll
            for (int p = 0; p < 4; p++) {
                mma_f16(sacc[2*p],   ql[t], k4[p][0], k4[p][1]);
                mma_f16(sacc[2*p+1], ql[t], k4[p][2], k4[p][3]);
            }
        }

        if (kt >= 2 * qt) {
            int r0 = qt * 128 + wid * 16 + (lane >> 2);
            #pragma unroll
            for (int nt = 0; nt < 8; nt++)
                #pragma unroll
                for (int j = 0; j < 4; j++) {
                    int row = r0 + (j >> 1) * 8;
                    int col = kt * 64 + nt * 8 + (lane & 3) * 2 + (j & 1);
                    if (col > row) sacc[nt][j] = -1e30f;
                }
        }

        float rmax[2] = {-1e30f, -1e30f};
        #pragma unroll
        for (int nt = 0; nt < 8; nt++) {
            rmax[0] = fmaxf(rmax[0], fmaxf(sacc[nt][0], sacc[nt][1]));
            rmax[1] = fmaxf(rmax[1], fmaxf(sacc[nt][2], sacc[nt][3]));
        }
        #pragma unroll
        for (int h = 0; h < 2; h++) {
            rmax[h] = fmaxf(rmax[h], __shfl_xor_sync(0xffffffffu, rmax[h], 1));
            rmax[h] = fmaxf(rmax[h], __shfl_xor_sync(0xffffffffu, rmax[h], 2));
        }
        float corr[2];
        #pragma unroll
        for (int h = 0; h < 2; h++) {
            float mnew = fmaxf(m_s[h], rmax[h]);
            corr[h] = fexp2(m_s[h] - mnew);
            m_s[h] = mnew;
        }

        // P single fp16
        uint32_t phpk[8][2];
        float rsum[2] = {0.0f, 0.0f};
        #pragma unroll
        for (int nt = 0; nt < 8; nt++) {
            #pragma unroll
            for (int h = 0; h < 2; h++) {
                float p0 = fexp2(sacc[nt][2*h]   - m_s[h]);
                float p1 = fexp2(sacc[nt][2*h+1] - m_s[h]);
                rsum[h] += p0 + p1;
                __half2 hp = __floats2half2_rn(p0, p1);
                phpk[nt][h] = *reinterpret_cast<uint32_t*>(&hp);
            }
        }
        #pragma unroll
        for (int h = 0; h < 2; h++) {
            rsum[h] += __shfl_xor_sync(0xffffffffu, rsum[h], 1);
            rsum[h] += __shfl_xor_sync(0xffffffffu, rsum[h], 2);
            l_s[h] = l_s[h] * corr[h] + rsum[h];
        }
        #pragma unroll
        for (int nt = 0; nt < 8; nt++) {
            oacc[nt][0] *= corr[0];
            oacc[nt][1] *= corr[0];
            oacc[nt][2] *= corr[1];
            oacc[nt][3] *= corr[1];
        }

        // ---- O += P V ----
        #pragma unroll
        for (int t = 0; t < 4; t++) {
            uint32_t pa[4] = { phpk[2*t][0], phpk[2*t][1], phpk[2*t+1][0], phpk[2*t+1][1] };
            uint32_t v4[4][4];
            #pragma unroll
            for (int p = 0; p < 4; p++) {
                int row = t * 16 + (lane & 15);
                int c = 2 * p + (lane >> 4);
                ldsm_x4_t(v4[p], stV + SWZ(row, c));
            }
            #pragma unroll
            for (int p = 0; p < 4; p++) {
                mma_f16(oacc[2*p],   pa, v4[p][0], v4[p][1]);
                mma_f16(oacc[2*p+1], pa, v4[p][2], v4[p][3]);
            }
        }
        __syncthreads();
    }

    const int b = bh >> 4;
    const int head = bh & 15;
    float inv[2] = {1.0f / l_s[0], 1.0f / l_s[1]};
    #pragma unroll
    for (int h = 0; h < 2; h++) {
        int srow = qt * 128 + wid * 16 + (lane >> 2) + h * 8;
        size_t base = ((size_t)(b * SS + srow)) * DD + head * 64 + (lane & 3) * 2;
        #pragma unroll
        for (int nt = 0; nt < 8; nt++) {
            float o0 = oacc[nt][2*h]   * inv[h];
            float o1 = oacc[nt][2*h+1] * inv[h];
            __half h0 = __float2half_rn(o0);
            __half h1 = __float2half_rn(o1);
            *reinterpret_cast<uint32_t*>(g_ah + base + nt * 8) = pack_f16(h0, h1);
            *reinterpret_cast<uint32_t*>(g_al + base + nt * 8) = pack_f16(
                __float2half_rn(o0 - __half2float(h0)),
                __float2half_rn(o1 - __half2float(h1)));
        }
    }
}

// ---------------------------------------------------------------------------
extern "C" void kernel_launch(void* const* d_in, const int* in_sizes, int n_in,
                              void* d_out, int out_size)
{
    (void)in_sizes; (void)n_in; (void)out_size;
    const float* x   = (const float*)d_in[0];
    const float* w1  = (const float*)d_in[1];
    const float* b1  = (const float*)d_in[2];
    const float* w2  = (const float*)d_in[3];
    const float* b2  = (const float*)d_in[4];
    float* out = (float*)d_out;

    const int SMEM_DYN = 2 * STAGE_B;          // 98304
    const int SMEM_FL  = 65536;                // 64KB
    cudaFuncSetAttribute(mma_gemm<0>, cudaFuncAttributeMaxDynamicSharedMemorySize, SMEM_DYN);
    cudaFuncSetAttribute(mma_gemm<1>, cudaFuncAttributeMaxDynamicSharedMemorySize, SMEM_DYN);
    cudaFuncSetAttribute(flash_mma, cudaFuncAttributeMaxDynamicSharedMemorySize, SMEM_FL);

    void *p_xh, *p_xl, *p_w1t, *p_w2t, *p_ah, *p_al;
    cudaGetSymbolAddress(&p_xh, g_xh);   cudaGetSymbolAddress(&p_xl, g_xl);
    cudaGetSymbolAddress(&p_w1t, g_w1t); cudaGetSymbolAddress(&p_w2t, g_w2t);
    cudaGetSymbolAddress(&p_ah, g_ah);   cudaGetSymbolAddress(&p_al, g_al);

    split_kernel<<<MROWS * DD / 1024, 256>>>(x, (__half*)p_xh, (__half*)p_xl);
    tconv_kernel<<<dim3(3 * DD / 32, DD / 32), 256>>>(w1, (__half*)p_w1t, DD, 3 * DD);
    tconv_kernel<<<dim3(DD / 32, DD / 32), 256>>>(w2, (__half*)p_w2t, DD, DD);

    mma_gemm<0><<<dim3(3 * DD / 128, MROWS / 128), 256, SMEM_DYN>>>(
        (const __half*)p_xh, (const __half*)p_xl, (const __half*)p_w1t,
        b1, nullptr, 3 * DD, DD);

    flash_mma<<<dim3(SS / 128, BH), 256, SMEM_FL>>>();

    mma_gemm<1><<<dim3(DD / 128, MROWS / 128), 256, SMEM_DYN>>>(
        (const __half*)p_ah, (const __half*)p_al, (const __half*)p_w2t,
        b2, out, DD, DD);
}

// round 13
// speedup vs baseline: 1.3776x; 1.0043x over previous
#include <cuda_runtime.h>
#include <cuda_fp16.h>
#include <cstdint>
#include <math.h>

// Problem constants
#define BB 2
#define SS 2048
#define DD 1024
#define HH 16
#define HD 64
#define BH (BB*HH)          // 32
#define MROWS (BB*SS)       // 4096
#define LOG2E 1.4426950408889634f

// ---------------------------------------------------------------------------
// Scratch (static device globals: allocation-free)
// ---------------------------------------------------------------------------
__device__ __half g_qh[BH*SS*HD];     // Q split hi (exp2-domain scaled)
__device__ __half g_ql[BH*SS*HD];     // Q split lo
__device__ __half g_k16[BH*SS*HD];    // K single fp16
__device__ __half g_v16[BH*SS*HD];    // V single fp16
__device__ __half g_xh [MROWS*DD];    // X split hi
__device__ __half g_xl [MROWS*DD];    // X split lo
__device__ __half g_w1t[3*DD*DD];     // W1^T single fp16 [3072,1024]
__device__ __half g_w2t[DD*DD];       // W2^T single fp16 [1024,1024]
__device__ __half g_ah [MROWS*DD];    // attn out split hi
__device__ __half g_al [MROWS*DD];    // attn out split lo

// ---------------------------------------------------------------------------
// PTX helpers (sm_80-portable: mma.sync / ldmatrix / cp.async)
// ---------------------------------------------------------------------------
__device__ __forceinline__ uint32_t smem_to_u32(const void* p) {
    uint32_t a;
    asm("{ .reg .u64 t; cvta.to.shared.u64 t, %1; cvt.u32.u64 %0, t; }"
        : "=r"(a) : "l"(p));
    return a;
}
__device__ __forceinline__ void ldsm_x4(uint32_t* r, uint32_t addr) {
    asm volatile("ldmatrix.sync.aligned.m8n8.x4.shared.b16 {%0,%1,%2,%3}, [%4];"
                 : "=r"(r[0]), "=r"(r[1]), "=r"(r[2]), "=r"(r[3]) : "r"(addr));
}
__device__ __forceinline__ void ldsm_x4_t(uint32_t* r, uint32_t addr) {
    asm volatile("ldmatrix.sync.aligned.m8n8.x4.trans.shared.b16 {%0,%1,%2,%3}, [%4];"
                 : "=r"(r[0]), "=r"(r[1]), "=r"(r[2]), "=r"(r[3]) : "r"(addr));
}
__device__ __forceinline__ void mma_f16(float* c, const uint32_t* a, uint32_t b0, uint32_t b1) {
    asm volatile(
        "mma.sync.aligned.m16n8k16.row.col.f32.f16.f16.f32 "
        "{%0,%1,%2,%3}, {%4,%5,%6,%7}, {%8,%9}, {%0,%1,%2,%3};"
        : "+f"(c[0]), "+f"(c[1]), "+f"(c[2]), "+f"(c[3])
        : "r"(a[0]), "r"(a[1]), "r"(a[2]), "r"(a[3]), "r"(b0), "r"(b1));
}
__device__ __forceinline__ void cp_async16(uint32_t saddr, const void* gptr) {
    asm volatile("cp.async.cg.shared.global [%0], [%1], 16;" :: "r"(saddr), "l"(gptr));
}
#define CP_COMMIT()  asm volatile("cp.async.commit_group;" ::: "memory")
#define CP_WAIT(n)   asm volatile("cp.async.wait_group %0;" :: "n"(n) : "memory")

// XOR swizzle inside 128B rows: element chunk c (16B) of row r
#define SWZ(r, c) ((uint32_t)(r)*128u + ((((uint32_t)(c)) ^ ((uint32_t)(r) & 7u)) << 4))

// Fast exp2 on FMA pipe. t <= 0 expected.
__device__ __forceinline__ float fexp2(float t) {
    t = fmaxf(t, -126.0f);
    float kf = rintf(t);
    float f = t - kf;
    float p = 0.0013333558f;
    p = fmaf(p, f, 0.0096181291f);
    p = fmaf(p, f, 0.0555041087f);
    p = fmaf(p, f, 0.2402265069f);
    p = fmaf(p, f, 0.6931471806f);
    p = fmaf(p, f, 1.0f);
    return __int_as_float(__float_as_int(p) + (((int)kf) << 23));
}
__device__ __forceinline__ uint32_t pack_f16(__half a, __half b) {
    return ((uint32_t)__half_as_ushort(b) << 16) | (uint32_t)__half_as_ushort(a);
}

// ---------------------------------------------------------------------------
// Conversion kernels
// ---------------------------------------------------------------------------
__global__ __launch_bounds__(256)
void split_kernel(const float* __restrict__ x, __half* __restrict__ xh,
                  __half* __restrict__ xl)
{
    int i = (blockIdx.x * 256 + threadIdx.x) * 4;
    float4 v = *reinterpret_cast<const float4*>(x + i);
    float a[4] = {v.x, v.y, v.z, v.w};
    #pragma unroll
    for (int j = 0; j < 4; j++) {
        __half h = __float2half_rn(a[j]);
        xh[i + j] = h;
        xl[i + j] = __float2half_rn(a[j] - __half2float(h));
    }
}

// W[K,N] fp32 -> WT single fp16 [N,K]
__global__ __launch_bounds__(256)
void tconv_kernel(const float* __restrict__ W, __half* __restrict__ WT, int K, int N)
{
    __shared__ float t[32][33];
    const int k0 = blockIdx.y * 32, n0 = blockIdx.x * 32;
    const int tx = threadIdx.x & 31, ty = threadIdx.x >> 5;
    #pragma unroll
    for (int i = 0; i < 4; i++)
        t[ty + i * 8][tx] = W[(size_t)(k0 + ty + i * 8) * N + n0 + tx];
    __syncthreads();
    #pragma unroll
    for (int i = 0; i < 4; i++) {
        int n = ty + i * 8;
        WT[(size_t)(n0 + n) * K + k0 + tx] = __float2half_rn(t[tx][n]);
    }
}

// ---------------------------------------------------------------------------
// mma.sync GEMM: D = (Ah[+Al])[M,K] @ B[N,K]^T + bias.
// BM=BN=128, BK=64 (128B rows, XOR swizzle -> conflict-free ldmatrix).
// 8 warps (2x4), warp tile 64x32, 2 CTAs/SM, cp.async double buffer.
// EPI=0: Q CTAs (bn<8) use full X split; K/V CTAs (bn>=8) use hi-only X
//        (their outputs are stored single-fp16 anyway -> same error class).
// EPI=1: full split, fp32 C.
// ---------------------------------------------------------------------------
#define TILE_B  16384           // 128 rows * 128B
#define STAGE_B 49152           // 3 tiles (Ah, Al, B)

template<int EPI>
__global__ __launch_bounds__(256, 2)
void mma_gemm(const __half* __restrict__ Ah, const __half* __restrict__ Al,
              const __half* __restrict__ Bs,
              const float* __restrict__ bias, float* __restrict__ C,
              int N, int K)
{
    extern __shared__ char dsm[];
    const uint32_t sb = smem_to_u32(dsm);

    const int tid = threadIdx.x;
    const int wid = tid >> 5;
    const int lane = tid & 31;
    const int bm = blockIdx.y;
    const int bn = blockIdx.x;
    const int wm = wid & 1;
    const int wn = wid >> 1;

    // Q CTAs need the X lo-term; K/V CTAs don't (outputs truncated to fp16 anyway)
    const bool needLo = (EPI == 1) || (bn < 8);

    const __half* gsrc[3];
    gsrc[0] = Ah + (size_t)bm * 128 * K;
    gsrc[1] = Al + (size_t)bm * 128 * K;
    gsrc[2] = Bs + (size_t)bn * 128 * K;

    // loader: 1024 16B-chunks per tile; thread does 4 per tile
    auto load_stage = [&](int stage, int k0) {
        uint32_t sdst = sb + stage * STAGE_B;
        #pragma unroll
        for (int op = 0; op < 3; op++) {
            if (op == 1 && !needLo) continue;
            const __half* g = gsrc[op];
            #pragma unroll
            for (int i = 0; i < 4; i++) {
                int ch = tid + i * 256;
                int r = ch >> 3, c = ch & 7;
                cp_async16(sdst + op * TILE_B + SWZ(r, c),
                           g + (size_t)r * K + k0 + c * 8);
            }
        }
    };

    float acc[4][4][4];
    #pragma unroll
    for (int mt = 0; mt < 4; mt++)
        #pragma unroll
        for (int nt = 0; nt < 4; nt++)
            #pragma unroll
            for (int r = 0; r < 4; r++) acc[mt][nt][r] = 0.0f;

    const int NCH = K >> 6;    // K/64

    load_stage(0, 0);
    CP_COMMIT();

    const int bg = lane >> 3;

    for (int c = 0; c < NCH; c++) {
        const int stage = c & 1;
        if (c + 1 < NCH) {
            load_stage((c + 1) & 1, (c + 1) * 64);
            CP_COMMIT();
            CP_WAIT(1);
        } else {
            CP_WAIT(0);
        }
        __syncthreads();

        const uint32_t sA_h = sb + stage * STAGE_B + 0 * TILE_B;
        const uint32_t sA_l = sb + stage * STAGE_B + 1 * TILE_B;
        const uint32_t sB   = sb + stage * STAGE_B + 2 * TILE_B;

        #pragma unroll
        for (int ks = 0; ks < 4; ks++) {
            uint32_t bf[2][4];
            #pragma unroll
            for (int nt2 = 0; nt2 < 2; nt2++) {
                int row = wn * 32 + nt2 * 16 + (lane & 7) + ((bg >> 1) << 3);
                ldsm_x4(bf[nt2], sB + SWZ(row, ks * 2 + (bg & 1)));
            }
            #pragma unroll
            for (int mt = 0; mt < 4; mt++) {
                uint32_t ahf[4];
                int row = wm * 64 + mt * 16 + (lane & 15);
                int cc = ks * 2 + (lane >> 4);
                ldsm_x4(ahf, sA_h + SWZ(row, cc));
                #pragma unroll
                for (int nt = 0; nt < 4; nt++)
                    mma_f16(acc[mt][nt], ahf, bf[nt >> 1][(nt & 1) * 2], bf[nt >> 1][(nt & 1) * 2 + 1]);
                if (needLo) {
                    uint32_t alf[4];
                    ldsm_x4(alf, sA_l + SWZ(row, cc));
                    #pragma unroll
                    for (int nt = 0; nt < 4; nt++)
                        mma_f16(acc[mt][nt], alf, bf[nt >> 1][(nt & 1) * 2], bf[nt >> 1][(nt & 1) * 2 + 1]);
                }
            }
        }
        __syncthreads();
    }

    // Epilogue: pair (r, r+1) = same row, adjacent cols -> wide stores
    #pragma unroll
    for (int mt = 0; mt < 4; mt++) {
        #pragma unroll
        for (int nt = 0; nt < 4; nt++) {
            #pragma unroll
            for (int rp = 0; rp < 2; rp++) {
                int m = bm * 128 + wm * 64 + mt * 16 + (lane >> 2) + rp * 8;
                int n = bn * 128 + wn * 32 + nt * 8 + (lane & 3) * 2;   // even
                float v0 = acc[mt][nt][rp * 2 + 0] + __ldg(&bias[n]);
                float v1 = acc[mt][nt][rp * 2 + 1] + __ldg(&bias[n + 1]);
                if (EPI == 0) {
                    int part = n >> 10;
                    int b = m >> 11;
                    int s = m & 2047;
                    int col = n & 1023;
                    int hh = col >> 6;
                    int d = col & 63;                      // even
                    size_t idx = (((size_t)(b * 16 + hh) * 2048) + s) * 64 + d;
                    if (part == 0) {
                        v0 *= 0.125f * LOG2E;
                        v1 *= 0.125f * LOG2E;
                        __half h0 = __float2half_rn(v0);
                        __half h1 = __float2half_rn(v1);
                        *reinterpret_cast<uint32_t*>(&g_qh[idx]) = pack_f16(h0, h1);
                        *reinterpret_cast<uint32_t*>(&g_ql[idx]) = pack_f16(
                            __float2half_rn(v0 - __half2float(h0)),
                            __float2half_rn(v1 - __half2float(h1)));
                    } else if (part == 1) {
                        __half2 hp = __floats2half2_rn(v0, v1);
                        *reinterpret_cast<__half2*>(&g_k16[idx]) = hp;
                    } else {
                        __half2 hp = __floats2half2_rn(v0, v1);
                        *reinterpret_cast<__half2*>(&g_v16[idx]) = hp;
                    }
                } else {
                    float2 o = make_float2(v0, v1);
                    *reinterpret_cast<float2*>(&C[(size_t)m * N + n]) = o;
                }
            }
        }
    }
}

// ---------------------------------------------------------------------------
// Tensor-core flash attention: Q fp16-split x K single; P single fp16 x V single.
// Bq=128, Bk=64, 8 warps (warp = 16 q-rows), 2 CTAs/SM.
// smem: Qh/Ql 32KB + 2 stages x (K,V) 16KB = 64KB per CTA.
// ---------------------------------------------------------------------------
__global__ __launch_bounds__(256, 2)
void flash_mma()
{
    extern __shared__ char fsm[];
    const uint32_t sb = smem_to_u32(fsm);
    const uint32_t sQh = sb, sQl = sb + 16384;

    const int tid = threadIdx.x;
    const int lane = tid & 31;
    const int wid = tid >> 5;
    const int qt = 15 - blockIdx.x;       // heavy tiles first
    const int bh = blockIdx.y;

    const size_t qoff = ((size_t)bh * SS + qt * 128) * HD;

    auto load_Q = [&]() {
        #pragma unroll
        for (int i = 0; i < 4; i++) {
            int ch = tid + i * 256;
            int r = ch >> 3, c = ch & 7;
            cp_async16(sQh + SWZ(r, c), g_qh + qoff + (size_t)r * 64 + c * 8);
            cp_async16(sQl + SWZ(r, c), g_ql + qoff + (size_t)r * 64 + c * 8);
        }
    };
    auto load_KV = [&](int stage, int kt) {
        uint32_t sbase = sb + 32768 + stage * 16384;
        size_t off = ((size_t)bh * SS + kt * 64) * HD;
        const __half* srcs[2] = { g_k16 + off, g_v16 + off };
        #pragma unroll
        for (int b = 0; b < 2; b++)
            #pragma unroll
            for (int i = 0; i < 2; i++) {
                int ch = tid + i * 256;
                int r = ch >> 3, c = ch & 7;
                cp_async16(sbase + b * 8192 + SWZ(r, c), srcs[b] + (size_t)r * 64 + c * 8);
            }
    };

    const int nkt = 2 * qt + 2;

    load_Q();
    load_KV(0, 0);
    CP_COMMIT();

    uint32_t qh[4][4], ql[4][4];
    float oacc[8][4];
    #pragma unroll
    for (int nt = 0; nt < 8; nt++)
        #pragma unroll
        for (int j = 0; j < 4; j++) oacc[nt][j] = 0.0f;
    float m_s[2] = {-1e30f, -1e30f};
    float l_s[2] = {0.0f, 0.0f};

    for (int kt = 0; kt < nkt; kt++) {
        const int stage = kt & 1;
        if (kt + 1 < nkt) {
            load_KV((kt + 1) & 1, kt + 1);
            CP_COMMIT();
            CP_WAIT(1);
        } else {
            CP_WAIT(0);
        }
        __syncthreads();

        if (kt == 0) {
            #pragma unroll
            for (int t = 0; t < 4; t++) {
                int row = wid * 16 + (lane & 15);
                int c = t * 2 + (lane >> 4);
                ldsm_x4(qh[t], sQh + SWZ(row, c));
                ldsm_x4(ql[t], sQl + SWZ(row, c));
            }
        }

        const uint32_t stK = sb + 32768 + stage * 16384;
        const uint32_t stV = stK + 8192;

        float sacc[8][4];
        #pragma unroll
        for (int nt = 0; nt < 8; nt++)
            #pragma unroll
            for (int j = 0; j < 4; j++) sacc[nt][j] = 0.0f;

        // ---- S = (Qh+Ql) K^T ----
        #pragma unroll
        for (int t = 0; t < 4; t++) {
            uint32_t k4[4][4];
            const int g = lane >> 3;
            #pragma unroll
            for (int p = 0; p < 4; p++) {
                int row = p * 16 + (lane & 7) + ((g >> 1) << 3);
                int c = t * 2 + (g & 1);
                ldsm_x4(k4[p], stK + SWZ(row, c));
            }
            #pragma unroll
            for (int p = 0; p < 4; p++) {
                mma_f16(sacc[2*p],   qh[t], k4[p][0], k4[p][1]);
                mma_f16(sacc[2*p+1], qh[t], k4[p][2], k4[p][3]);
            }
            #pragma unroll
            for (int p = 0; p < 4; p++) {
                mma_f16(sacc[2*p],   ql[t], k4[p][0], k4[p][1]);
                mma_f16(sacc[2*p+1], ql[t], k4[p][2], k4[p][3]);
            }
        }

        if (kt >= 2 * qt) {
            int r0 = qt * 128 + wid * 16 + (lane >> 2);
            #pragma unroll
            for (int nt = 0; nt < 8; nt++)
                #pragma unroll
                for (int j = 0; j < 4; j++) {
                    int row = r0 + (j >> 1) * 8;
                    int col = kt * 64 + nt * 8 + (lane & 3) * 2 + (j & 1);
                    if (col > row) sacc[nt][j] = -1e30f;
                }
        }

        float rmax[2] = {-1e30f, -1e30f};
        #pragma unroll
        for (int nt = 0; nt < 8; nt++) {
            rmax[0] = fmaxf(rmax[0], fmaxf(sacc[nt][0], sacc[nt][1]));
            rmax[1] = fmaxf(rmax[1], fmaxf(sacc[nt][2], sacc[nt][3]));
        }
        #pragma unroll
        for (int h = 0; h < 2; h++) {
            rmax[h] = fmaxf(rmax[h], __shfl_xor_sync(0xffffffffu, rmax[h], 1));
            rmax[h] = fmaxf(rmax[h], __shfl_xor_sync(0xffffffffu, rmax[h], 2));
        }
        float corr[2];
        #pragma unroll
        for (int h = 0; h < 2; h++) {
            float mnew = fmaxf(m_s[h], rmax[h]);
            corr[h] = fexp2(m_s[h] - mnew);
            m_s[h] = mnew;
        }

        // P single fp16
        uint32_t phpk[8][2];
        float rsum[2] = {0.0f, 0.0f};
        #pragma unroll
        for (int nt = 0; nt < 8; nt++) {
            #pragma unroll
            for (int h = 0; h < 2; h++) {
                float p0 = fexp2(sacc[nt][2*h]   - m_s[h]);
                float p1 = fexp2(sacc[nt][2*h+1] - m_s[h]);
                rsum[h] += p0 + p1;
                __half2 hp = __floats2half2_rn(p0, p1);
                phpk[nt][h] = *reinterpret_cast<uint32_t*>(&hp);
            }
        }
        #pragma unroll
        for (int h = 0; h < 2; h++) {
            rsum[h] += __shfl_xor_sync(0xffffffffu, rsum[h], 1);
            rsum[h] += __shfl_xor_sync(0xffffffffu, rsum[h], 2);
            l_s[h] = l_s[h] * corr[h] + rsum[h];
        }
        #pragma unroll
        for (int nt = 0; nt < 8; nt++) {
            oacc[nt][0] *= corr[0];
            oacc[nt][1] *= corr[0];
            oacc[nt][2] *= corr[1];
            oacc[nt][3] *= corr[1];
        }

        // ---- O += P V ----
        #pragma unroll
        for (int t = 0; t < 4; t++) {
            uint32_t pa[4] = { phpk[2*t][0], phpk[2*t][1], phpk[2*t+1][0], phpk[2*t+1][1] };
            uint32_t v4[4][4];
            #pragma unroll
            for (int p = 0; p < 4; p++) {
                int row = t * 16 + (lane & 15);
                int c = 2 * p + (lane >> 4);
                ldsm_x4_t(v4[p], stV + SWZ(row, c));
            }
            #pragma unroll
            for (int p = 0; p < 4; p++) {
                mma_f16(oacc[2*p],   pa, v4[p][0], v4[p][1]);
                mma_f16(oacc[2*p+1], pa, v4[p][2], v4[p][3]);
            }
        }
        __syncthreads();
    }

    const int b = bh >> 4;
    const int head = bh & 15;
    float inv[2] = {1.0f / l_s[0], 1.0f / l_s[1]};
    #pragma unroll
    for (int h = 0; h < 2; h++) {
        int srow = qt * 128 + wid * 16 + (lane >> 2) + h * 8;
        size_t base = ((size_t)(b * SS + srow)) * DD + head * 64 + (lane & 3) * 2;
        #pragma unroll
        for (int nt = 0; nt < 8; nt++) {
            float o0 = oacc[nt][2*h]   * inv[h];
            float o1 = oacc[nt][2*h+1] * inv[h];
            __half h0 = __float2half_rn(o0);
            __half h1 = __float2half_rn(o1);
            *reinterpret_cast<uint32_t*>(g_ah + base + nt * 8) = pack_f16(h0, h1);
            *reinterpret_cast<uint32_t*>(g_al + base + nt * 8) = pack_f16(
                __float2half_rn(o0 - __half2float(h0)),
                __float2half_rn(o1 - __half2float(h1)));
        }
    }
}

// ---------------------------------------------------------------------------
extern "C" void kernel_launch(void* const* d_in, const int* in_sizes, int n_in,
                              void* d_out, int out_size)
{
    (void)in_sizes; (void)n_in; (void)out_size;
    const float* x   = (const float*)d_in[0];
    const float* w1  = (const float*)d_in[1];
    const float* b1  = (const float*)d_in[2];
    const float* w2  = (const float*)d_in[3];
    const float* b2  = (const float*)d_in[4];
    float* out = (float*)d_out;

    const int SMEM_DYN = 2 * STAGE_B;          // 98304
    const int SMEM_FL  = 65536;                // 64KB
    cudaFuncSetAttribute(mma_gemm<0>, cudaFuncAttributeMaxDynamicSharedMemorySize, SMEM_DYN);
    cudaFuncSetAttribute(mma_gemm<1>, cudaFuncAttributeMaxDynamicSharedMemorySize, SMEM_DYN);
    cudaFuncSetAttribute(flash_mma, cudaFuncAttributeMaxDynamicSharedMemorySize, SMEM_FL);

    void *p_xh, *p_xl, *p_w1t, *p_w2t, *p_ah, *p_al;
    cudaGetSymbolAddress(&p_xh, g_xh);   cudaGetSymbolAddress(&p_xl, g_xl);
    cudaGetSymbolAddress(&p_w1t, g_w1t); cudaGetSymbolAddress(&p_w2t, g_w2t);
    cudaGetSymbolAddress(&p_ah, g_ah);   cudaGetSymbolAddress(&p_al, g_al);

    split_kernel<<<MROWS * DD / 1024, 256>>>(x, (__half*)p_xh, (__half*)p_xl);
    tconv_kernel<<<dim3(3 * DD / 32, DD / 32), 256>>>(w1, (__half*)p_w1t, DD, 3 * DD);
    tconv_kernel<<<dim3(DD / 32, DD / 32), 256>>>(w2, (__half*)p_w2t, DD, DD);

    mma_gemm<0><<<dim3(3 * DD / 128, MROWS / 128), 256, SMEM_DYN>>>(
        (const __half*)p_xh, (const __half*)p_xl, (const __half*)p_w1t,
        b1, nullptr, 3 * DD, DD);

    flash_mma<<<dim3(SS / 128, BH), 256, SMEM_FL>>>();

    mma_gemm<1><<<dim3(DD / 128, MROWS / 128), 256, SMEM_DYN>>>(
        (const __half*)p_ah, (const __half*)p_al, (const __half*)p_w2t,
        b2, out, DD, DD);
}

// round 14
// speedup vs baseline: 1.4978x; 1.0873x over previous
#include <cuda_runtime.h>
#include <cuda_fp16.h>
#include <cstdint>
#include <math.h>

// Problem constants
#define BB 2
#define SS 2048
#define DD 1024
#define HH 16
#define HD 64
#define BH (BB*HH)          // 32
#define MROWS (BB*SS)       // 4096
#define LOG2E 1.4426950408889634f

// ---------------------------------------------------------------------------
// Scratch (static device globals: allocation-free)
// ---------------------------------------------------------------------------
__device__ __half g_qh[BH*SS*HD];     // Q split hi (exp2-domain scaled)
__device__ __half g_ql[BH*SS*HD];     // Q split lo
__device__ __half g_k16[BH*SS*HD];    // K single fp16
__device__ __half g_v16[BH*SS*HD];    // V single fp16
__device__ __half g_xh [MROWS*DD];    // X split hi
__device__ __half g_xl [MROWS*DD];    // X split lo
__device__ __half g_w1t[3*DD*DD];     // W1^T single fp16 [3072,1024]
__device__ __half g_w2t[DD*DD];       // W2^T single fp16 [1024,1024]
__device__ __half g_ah [MROWS*DD];    // attn out split hi
__device__ __half g_al [MROWS*DD];    // attn out split lo

// ---------------------------------------------------------------------------
// PTX helpers (sm_80-portable: mma.sync / ldmatrix / cp.async)
// ---------------------------------------------------------------------------
__device__ __forceinline__ uint32_t smem_to_u32(const void* p) {
    uint32_t a;
    asm("{ .reg .u64 t; cvta.to.shared.u64 t, %1; cvt.u32.u64 %0, t; }"
        : "=r"(a) : "l"(p));
    return a;
}
__device__ __forceinline__ void ldsm_x4(uint32_t* r, uint32_t addr) {
    asm volatile("ldmatrix.sync.aligned.m8n8.x4.shared.b16 {%0,%1,%2,%3}, [%4];"
                 : "=r"(r[0]), "=r"(r[1]), "=r"(r[2]), "=r"(r[3]) : "r"(addr));
}
__device__ __forceinline__ void ldsm_x4_t(uint32_t* r, uint32_t addr) {
    asm volatile("ldmatrix.sync.aligned.m8n8.x4.trans.shared.b16 {%0,%1,%2,%3}, [%4];"
                 : "=r"(r[0]), "=r"(r[1]), "=r"(r[2]), "=r"(r[3]) : "r"(addr));
}
__device__ __forceinline__ void mma_f16(float* c, const uint32_t* a, uint32_t b0, uint32_t b1) {
    asm volatile(
        "mma.sync.aligned.m16n8k16.row.col.f32.f16.f16.f32 "
        "{%0,%1,%2,%3}, {%4,%5,%6,%7}, {%8,%9}, {%0,%1,%2,%3};"
        : "+f"(c[0]), "+f"(c[1]), "+f"(c[2]), "+f"(c[3])
        : "r"(a[0]), "r"(a[1]), "r"(a[2]), "r"(a[3]), "r"(b0), "r"(b1));
}
__device__ __forceinline__ void cp_async16(uint32_t saddr, const void* gptr) {
    asm volatile("cp.async.cg.shared.global [%0], [%1], 16;" :: "r"(saddr), "l"(gptr));
}
#define CP_COMMIT()  asm volatile("cp.async.commit_group;" ::: "memory")
#define CP_WAIT(n)   asm volatile("cp.async.wait_group %0;" :: "n"(n) : "memory")

// XOR swizzle inside 128B rows: element chunk c (16B) of row r
#define SWZ(r, c) ((uint32_t)(r)*128u + ((((uint32_t)(c)) ^ ((uint32_t)(r) & 7u)) << 4))

// Fast exp2 on FMA pipe. t <= 0 expected.
__device__ __forceinline__ float fexp2(float t) {
    t = fmaxf(t, -126.0f);
    float kf = rintf(t);
    float f = t - kf;
    float p = 0.0013333558f;
    p = fmaf(p, f, 0.0096181291f);
    p = fmaf(p, f, 0.0555041087f);
    p = fmaf(p, f, 0.2402265069f);
    p = fmaf(p, f, 0.6931471806f);
    p = fmaf(p, f, 1.0f);
    return __int_as_float(__float_as_int(p) + (((int)kf) << 23));
}
__device__ __forceinline__ uint32_t pack_f16(__half a, __half b) {
    return ((uint32_t)__half_as_ushort(b) << 16) | (uint32_t)__half_as_ushort(a);
}

// ---------------------------------------------------------------------------
// Conversion kernels
// ---------------------------------------------------------------------------
__global__ __launch_bounds__(256)
void split_kernel(const float* __restrict__ x, __half* __restrict__ xh,
                  __half* __restrict__ xl)
{
    int i = (blockIdx.x * 256 + threadIdx.x) * 4;
    float4 v = *reinterpret_cast<const float4*>(x + i);
    float a[4] = {v.x, v.y, v.z, v.w};
    #pragma unroll
    for (int j = 0; j < 4; j++) {
        __half h = __float2half_rn(a[j]);
        xh[i + j] = h;
        xl[i + j] = __float2half_rn(a[j] - __half2float(h));
    }
}

// W[K,N] fp32 -> WT single fp16 [N,K]
__global__ __launch_bounds__(256)
void tconv_kernel(const float* __restrict__ W, __half* __restrict__ WT, int K, int N)
{
    __shared__ float t[32][33];
    const int k0 = blockIdx.y * 32, n0 = blockIdx.x * 32;
    const int tx = threadIdx.x & 31, ty = threadIdx.x >> 5;
    #pragma unroll
    for (int i = 0; i < 4; i++)
        t[ty + i * 8][tx] = W[(size_t)(k0 + ty + i * 8) * N + n0 + tx];
    __syncthreads();
    #pragma unroll
    for (int i = 0; i < 4; i++) {
        int n = ty + i * 8;
        WT[(size_t)(n0 + n) * K + k0 + tx] = __float2half_rn(t[tx][n]);
    }
}

// ---------------------------------------------------------------------------
// mma.sync GEMM: D = (Ah[+Al])[M,K] @ B[N,K]^T + bias.
// BM=BN=128, BK=64 (128B rows, XOR swizzle -> conflict-free ldmatrix).
// 8 warps (2x4), warp tile 64x32, 2 CTAs/SM, cp.async double buffer.
// LO is a TEMPLATE flag (dead-code eliminated, not predicated): LO=true uses
// the full X hi+lo split, LO=false hi-only. bn0 offsets the N-tile index so
// the Q range (bn<8, split) and K/V range (bn>=8, hi-only) run as separate
// launches of specialized kernels.
// ---------------------------------------------------------------------------
#define TILE_B  16384           // 128 rows * 128B
#define STAGE_B 49152           // 3 tiles (Ah, Al, B)

template<int EPI, bool LO>
__global__ __launch_bounds__(256, 2)
void mma_gemm(const __half* __restrict__ Ah, const __half* __restrict__ Al,
              const __half* __restrict__ Bs,
              const float* __restrict__ bias, float* __restrict__ C,
              int N, int K, int bn0)
{
    extern __shared__ char dsm[];
    const uint32_t sb = smem_to_u32(dsm);

    const int tid = threadIdx.x;
    const int wid = tid >> 5;
    const int lane = tid & 31;
    const int bm = blockIdx.y;
    const int bn = blockIdx.x + bn0;
    const int wm = wid & 1;
    const int wn = wid >> 1;

    const __half* gsrc[3];
    gsrc[0] = Ah + (size_t)bm * 128 * K;
    gsrc[1] = Al + (size_t)bm * 128 * K;
    gsrc[2] = Bs + (size_t)bn * 128 * K;

    // loader: 1024 16B-chunks per tile; thread does 4 per tile
    auto load_stage = [&](int stage, int k0) {
        uint32_t sdst = sb + stage * STAGE_B;
        #pragma unroll
        for (int op = 0; op < 3; op++) {
            if (op == 1 && !LO) continue;
            const __half* g = gsrc[op];
            #pragma unroll
            for (int i = 0; i < 4; i++) {
                int ch = tid + i * 256;
                int r = ch >> 3, c = ch & 7;
                cp_async16(sdst + op * TILE_B + SWZ(r, c),
                           g + (size_t)r * K + k0 + c * 8);
            }
        }
    };

    float acc[4][4][4];
    #pragma unroll
    for (int mt = 0; mt < 4; mt++)
        #pragma unroll
        for (int nt = 0; nt < 4; nt++)
            #pragma unroll
            for (int r = 0; r < 4; r++) acc[mt][nt][r] = 0.0f;

    const int NCH = K >> 6;    // K/64

    load_stage(0, 0);
    CP_COMMIT();

    const int bg = lane >> 3;

    for (int c = 0; c < NCH; c++) {
        const int stage = c & 1;
        if (c + 1 < NCH) {
            load_stage((c + 1) & 1, (c + 1) * 64);
            CP_COMMIT();
            CP_WAIT(1);
        } else {
            CP_WAIT(0);
        }
        __syncthreads();

        const uint32_t sA_h = sb + stage * STAGE_B + 0 * TILE_B;
        const uint32_t sA_l = sb + stage * STAGE_B + 1 * TILE_B;
        const uint32_t sB   = sb + stage * STAGE_B + 2 * TILE_B;

        #pragma unroll
        for (int ks = 0; ks < 4; ks++) {
            uint32_t bf[2][4];
            #pragma unroll
            for (int nt2 = 0; nt2 < 2; nt2++) {
                int row = wn * 32 + nt2 * 16 + (lane & 7) + ((bg >> 1) << 3);
                ldsm_x4(bf[nt2], sB + SWZ(row, ks * 2 + (bg & 1)));
            }
            #pragma unroll
            for (int mt = 0; mt < 4; mt++) {
                uint32_t ahf[4];
                int row = wm * 64 + mt * 16 + (lane & 15);
                int cc = ks * 2 + (lane >> 4);
                ldsm_x4(ahf, sA_h + SWZ(row, cc));
                #pragma unroll
                for (int nt = 0; nt < 4; nt++)
                    mma_f16(acc[mt][nt], ahf, bf[nt >> 1][(nt & 1) * 2], bf[nt >> 1][(nt & 1) * 2 + 1]);
                if (LO) {
                    uint32_t alf[4];
                    ldsm_x4(alf, sA_l + SWZ(row, cc));
                    #pragma unroll
                    for (int nt = 0; nt < 4; nt++)
                        mma_f16(acc[mt][nt], alf, bf[nt >> 1][(nt & 1) * 2], bf[nt >> 1][(nt & 1) * 2 + 1]);
                }
            }
        }
        __syncthreads();
    }

    // Epilogue: pair (r, r+1) = same row, adjacent cols -> wide stores
    #pragma unroll
    for (int mt = 0; mt < 4; mt++) {
        #pragma unroll
        for (int nt = 0; nt < 4; nt++) {
            #pragma unroll
            for (int rp = 0; rp < 2; rp++) {
                int m = bm * 128 + wm * 64 + mt * 16 + (lane >> 2) + rp * 8;
                int n = bn * 128 + wn * 32 + nt * 8 + (lane & 3) * 2;   // even
                float v0 = acc[mt][nt][rp * 2 + 0] + __ldg(&bias[n]);
                float v1 = acc[mt][nt][rp * 2 + 1] + __ldg(&bias[n + 1]);
                if (EPI == 0) {
                    int part = n >> 10;
                    int b = m >> 11;
                    int s = m & 2047;
                    int col = n & 1023;
                    int hh = col >> 6;
                    int d = col & 63;                      // even
                    size_t idx = (((size_t)(b * 16 + hh) * 2048) + s) * 64 + d;
                    if (part == 0) {
                        v0 *= 0.125f * LOG2E;
                        v1 *= 0.125f * LOG2E;
                        __half h0 = __float2half_rn(v0);
                        __half h1 = __float2half_rn(v1);
                        *reinterpret_cast<uint32_t*>(&g_qh[idx]) = pack_f16(h0, h1);
                        *reinterpret_cast<uint32_t*>(&g_ql[idx]) = pack_f16(
                            __float2half_rn(v0 - __half2float(h0)),
                            __float2half_rn(v1 - __half2float(h1)));
                    } else if (part == 1) {
                        __half2 hp = __floats2half2_rn(v0, v1);
                        *reinterpret_cast<__half2*>(&g_k16[idx]) = hp;
                    } else {
                        __half2 hp = __floats2half2_rn(v0, v1);
                        *reinterpret_cast<__half2*>(&g_v16[idx]) = hp;
                    }
                } else {
                    float2 o = make_float2(v0, v1);
                    *reinterpret_cast<float2*>(&C[(size_t)m * N + n]) = o;
                }
            }
        }
    }
}

// ---------------------------------------------------------------------------
// Tensor-core flash attention: Q fp16-split x K single; P single fp16 x V single.
// Bq=128, Bk=64, 8 warps (warp = 16 q-rows), 2 CTAs/SM.
// smem: Qh/Ql 32KB + 2 stages x (K,V) 16KB = 64KB per CTA.
// ---------------------------------------------------------------------------
__global__ __launch_bounds__(256, 2)
void flash_mma()
{
    extern __shared__ char fsm[];
    const uint32_t sb = smem_to_u32(fsm);
    const uint32_t sQh = sb, sQl = sb + 16384;

    const int tid = threadIdx.x;
    const int lane = tid & 31;
    const int wid = tid >> 5;
    const int qt = 15 - blockIdx.x;       // heavy tiles first
    const int bh = blockIdx.y;

    const size_t qoff = ((size_t)bh * SS + qt * 128) * HD;

    auto load_Q = [&]() {
        #pragma unroll
        for (int i = 0; i < 4; i++) {
            int ch = tid + i * 256;
            int r = ch >> 3, c = ch & 7;
            cp_async16(sQh + SWZ(r, c), g_qh + qoff + (size_t)r * 64 + c * 8);
            cp_async16(sQl + SWZ(r, c), g_ql + qoff + (size_t)r * 64 + c * 8);
        }
    };
    auto load_KV = [&](int stage, int kt) {
        uint32_t sbase = sb + 32768 + stage * 16384;
        size_t off = ((size_t)bh * SS + kt * 64) * HD;
        const __half* srcs[2] = { g_k16 + off, g_v16 + off };
        #pragma unroll
        for (int b = 0; b < 2; b++)
            #pragma unroll
            for (int i = 0; i < 2; i++) {
                int ch = tid + i * 256;
                int r = ch >> 3, c = ch & 7;
                cp_async16(sbase + b * 8192 + SWZ(r, c), srcs[b] + (size_t)r * 64 + c * 8);
            }
    };

    const int nkt = 2 * qt + 2;

    load_Q();
    load_KV(0, 0);
    CP_COMMIT();

    uint32_t qh[4][4], ql[4][4];
    float oacc[8][4];
    #pragma unroll
    for (int nt = 0; nt < 8; nt++)
        #pragma unroll
        for (int j = 0; j < 4; j++) oacc[nt][j] = 0.0f;
    float m_s[2] = {-1e30f, -1e30f};
    float l_s[2] = {0.0f, 0.0f};

    for (int kt = 0; kt < nkt; kt++) {
        const int stage = kt & 1;
        if (kt + 1 < nkt) {
            load_KV((kt + 1) & 1, kt + 1);
            CP_COMMIT();
            CP_WAIT(1);
        } else {
            CP_WAIT(0);
        }
        __syncthreads();

        if (kt == 0) {
            #pragma unroll
            for (int t = 0; t < 4; t++) {
                int row = wid * 16 + (lane & 15);
                int c = t * 2 + (lane >> 4);
                ldsm_x4(qh[t], sQh + SWZ(row, c));
                ldsm_x4(ql[t], sQl + SWZ(row, c));
            }
        }

        const uint32_t stK = sb + 32768 + stage * 16384;
        const uint32_t stV = stK + 8192;

        float sacc[8][4];
        #pragma unroll
        for (int nt = 0; nt < 8; nt++)
            #pragma unroll
            for (int j = 0; j < 4; j++) sacc[nt][j] = 0.0f;

        // ---- S = (Qh+Ql) K^T ----
        #pragma unroll
        for (int t = 0; t < 4; t++) {
            uint32_t k4[4][4];
            const int g = lane >> 3;
            #pragma unroll
            for (int p = 0; p < 4; p++) {
                int row = p * 16 + (lane & 7) + ((g >> 1) << 3);
                int c = t * 2 + (g & 1);
                ldsm_x4(k4[p], stK + SWZ(row, c));
            }
            #pragma unroll
            for (int p = 0; p < 4; p++) {
                mma_f16(sacc[2*p],   qh[t], k4[p][0], k4[p][1]);
                mma_f16(sacc[2*p+1], qh[t], k4[p][2], k4[p][3]);
            }
            #pragma unroll
            for (int p = 0; p < 4; p++) {
                mma_f16(sacc[2*p],   ql[t], k4[p][0], k4[p][1]);
                mma_f16(sacc[2*p+1], ql[t], k4[p][2], k4[p][3]);
            }
        }

        if (kt >= 2 * qt) {
            int r0 = qt * 128 + wid * 16 + (lane >> 2);
            #pragma unroll
            for (int nt = 0; nt < 8; nt++)
                #pragma unroll
                for (int j = 0; j < 4; j++) {
                    int row = r0 + (j >> 1) * 8;
                    int col = kt * 64 + nt * 8 + (lane & 3) * 2 + (j & 1);
                    if (col > row) sacc[nt][j] = -1e30f;
                }
        }

        float rmax[2] = {-1e30f, -1e30f};
        #pragma unroll
        for (int nt = 0; nt < 8; nt++) {
            rmax[0] = fmaxf(rmax[0], fmaxf(sacc[nt][0], sacc[nt][1]));
            rmax[1] = fmaxf(rmax[1], fmaxf(sacc[nt][2], sacc[nt][3]));
        }
        #pragma unroll
        for (int h = 0; h < 2; h++) {
            rmax[h] = fmaxf(rmax[h], __shfl_xor_sync(0xffffffffu, rmax[h], 1));
            rmax[h] = fmaxf(rmax[h], __shfl_xor_sync(0xffffffffu, rmax[h], 2));
        }
        float corr[2];
        #pragma unroll
        for (int h = 0; h < 2; h++) {
            float mnew = fmaxf(m_s[h], rmax[h]);
            corr[h] = fexp2(m_s[h] - mnew);
            m_s[h] = mnew;
        }

        // P single fp16
        uint32_t phpk[8][2];
        float rsum[2] = {0.0f, 0.0f};
        #pragma unroll
        for (int nt = 0; nt < 8; nt++) {
            #pragma unroll
            for (int h = 0; h < 2; h++) {
                float p0 = fexp2(sacc[nt][2*h]   - m_s[h]);
                float p1 = fexp2(sacc[nt][2*h+1] - m_s[h]);
                rsum[h] += p0 + p1;
                __half2 hp = __floats2half2_rn(p0, p1);
                phpk[nt][h] = *reinterpret_cast<uint32_t*>(&hp);
            }
        }
        #pragma unroll
        for (int h = 0; h < 2; h++) {
            rsum[h] += __shfl_xor_sync(0xffffffffu, rsum[h], 1);
            rsum[h] += __shfl_xor_sync(0xffffffffu, rsum[h], 2);
            l_s[h] = l_s[h] * corr[h] + rsum[h];
        }
        #pragma unroll
        for (int nt = 0; nt < 8; nt++) {
            oacc[nt][0] *= corr[0];
            oacc[nt][1] *= corr[0];
            oacc[nt][2] *= corr[1];
            oacc[nt][3] *= corr[1];
        }

        // ---- O += P V ----
        #pragma unroll
        for (int t = 0; t < 4; t++) {
            uint32_t pa[4] = { phpk[2*t][0], phpk[2*t][1], phpk[2*t+1][0], phpk[2*t+1][1] };
            uint32_t v4[4][4];
            #pragma unroll
            for (int p = 0; p < 4; p++) {
                int row = t * 16 + (lane & 15);
                int c = 2 * p + (lane >> 4);
                ldsm_x4_t(v4[p], stV + SWZ(row, c));
            }
            #pragma unroll
            for (int p = 0; p < 4; p++) {
                mma_f16(oacc[2*p],   pa, v4[p][0], v4[p][1]);
                mma_f16(oacc[2*p+1], pa, v4[p][2], v4[p][3]);
            }
        }
        __syncthreads();
    }

    const int b = bh >> 4;
    const int head = bh & 15;
    float inv[2] = {1.0f / l_s[0], 1.0f / l_s[1]};
    #pragma unroll
    for (int h = 0; h < 2; h++) {
        int srow = qt * 128 + wid * 16 + (lane >> 2) + h * 8;
        size_t base = ((size_t)(b * SS + srow)) * DD + head * 64 + (lane & 3) * 2;
        #pragma unroll
        for (int nt = 0; nt < 8; nt++) {
            float o0 = oacc[nt][2*h]   * inv[h];
            float o1 = oacc[nt][2*h+1] * inv[h];
            __half h0 = __float2half_rn(o0);
            __half h1 = __float2half_rn(o1);
            *reinterpret_cast<uint32_t*>(g_ah + base + nt * 8) = pack_f16(h0, h1);
            *reinterpret_cast<uint32_t*>(g_al + base + nt * 8) = pack_f16(
                __float2half_rn(o0 - __half2float(h0)),
                __float2half_rn(o1 - __half2float(h1)));
        }
    }
}

// ---------------------------------------------------------------------------
extern "C" void kernel_launch(void* const* d_in, const int* in_sizes, int n_in,
                              void* d_out, int out_size)
{
    (void)in_sizes; (void)n_in; (void)out_size;
    const float* x   = (const float*)d_in[0];
    const float* w1  = (const float*)d_in[1];
    const float* b1  = (const float*)d_in[2];
    const float* w2  = (const float*)d_in[3];
    const float* b2  = (const float*)d_in[4];
    float* out = (float*)d_out;

    const int SMEM_DYN = 2 * STAGE_B;          // 98304
    const int SMEM_FL  = 65536;                // 64KB
    cudaFuncSetAttribute((const void*)mma_gemm<0, true>,  cudaFuncAttributeMaxDynamicSharedMemorySize, SMEM_DYN);
    cudaFuncSetAttribute((const void*)mma_gemm<0, false>, cudaFuncAttributeMaxDynamicSharedMemorySize, SMEM_DYN);
    cudaFuncSetAttribute((const void*)mma_gemm<1, true>,  cudaFuncAttributeMaxDynamicSharedMemorySize, SMEM_DYN);
    cudaFuncSetAttribute((const void*)flash_mma, cudaFuncAttributeMaxDynamicSharedMemorySize, SMEM_FL);

    void *p_xh, *p_xl, *p_w1t, *p_w2t, *p_ah, *p_al;
    cudaGetSymbolAddress(&p_xh, g_xh);   cudaGetSymbolAddress(&p_xl, g_xl);
    cudaGetSymbolAddress(&p_w1t, g_w1t); cudaGetSymbolAddress(&p_w2t, g_w2t);
    cudaGetSymbolAddress(&p_ah, g_ah);   cudaGetSymbolAddress(&p_al, g_al);

    split_kernel<<<MROWS * DD / 1024, 256>>>(x, (__half*)p_xh, (__half*)p_xl);
    tconv_kernel<<<dim3(3 * DD / 32, DD / 32), 256>>>(w1, (__half*)p_w1t, DD, 3 * DD);
    tconv_kernel<<<dim3(DD / 32, DD / 32), 256>>>(w2, (__half*)p_w2t, DD, DD);

    // Q columns: full X split (grid 8 x 32)
    mma_gemm<0, true><<<dim3(8, MROWS / 128), 256, SMEM_DYN>>>(
        (const __half*)p_xh, (const __half*)p_xl, (const __half*)p_w1t,
        b1, nullptr, 3 * DD, DD, 0);
    // K/V columns: hi-only X (grid 16 x 32), half the MMAs, 2/3 the loads
    mma_gemm<0, false><<<dim3(16, MROWS / 128), 256, SMEM_DYN>>>(
        (const __half*)p_xh, (const __half*)p_xl, (const __half*)p_w1t,
        b1, nullptr, 3 * DD, DD, 8);

    flash_mma<<<dim3(SS / 128, BH), 256, SMEM_FL>>>();

    mma_gemm<1, true><<<dim3(DD / 128, MROWS / 128), 256, SMEM_DYN>>>(
        (const __half*)p_ah, (const __half*)p_al, (const __half*)p_w2t,
        b2, out, DD, DD, 0);
}

// round 15
// speedup vs baseline: 1.5989x; 1.0675x over previous
#include <cuda_runtime.h>
#include <cuda_fp16.h>
#include <cstdint>
#include <math.h>

// Problem constants
#define BB 2
#define SS 2048
#define DD 1024
#define HH 16
#define HD 64
#define BH (BB*HH)          // 32
#define MROWS (BB*SS)       // 4096
#define LOG2E 1.4426950408889634f

// ---------------------------------------------------------------------------
// Scratch (static device globals: allocation-free)
// ---------------------------------------------------------------------------
__device__ __half g_qh[BH*SS*HD];     // Q split hi (exp2-domain scaled)
__device__ __half g_ql[BH*SS*HD];     // Q split lo
__device__ __half g_k16[BH*SS*HD];    // K single fp16
__device__ __half g_v16[BH*SS*HD];    // V single fp16
__device__ __half g_xh [MROWS*DD];    // X split hi
__device__ __half g_xl [MROWS*DD];    // X split lo
__device__ __half g_w1t[3*DD*DD];     // W1^T single fp16 [3072,1024]
__device__ __half g_w2t[DD*DD];       // W2^T single fp16 [1024,1024]
__device__ __half g_a16[MROWS*DD];    // attn out single fp16

// ---------------------------------------------------------------------------
// PTX helpers (sm_80-portable: mma.sync / ldmatrix / cp.async)
// ---------------------------------------------------------------------------
__device__ __forceinline__ uint32_t smem_to_u32(const void* p) {
    uint32_t a;
    asm("{ .reg .u64 t; cvta.to.shared.u64 t, %1; cvt.u32.u64 %0, t; }"
        : "=r"(a) : "l"(p));
    return a;
}
__device__ __forceinline__ void ldsm_x4(uint32_t* r, uint32_t addr) {
    asm volatile("ldmatrix.sync.aligned.m8n8.x4.shared.b16 {%0,%1,%2,%3}, [%4];"
                 : "=r"(r[0]), "=r"(r[1]), "=r"(r[2]), "=r"(r[3]) : "r"(addr));
}
__device__ __forceinline__ void ldsm_x4_t(uint32_t* r, uint32_t addr) {
    asm volatile("ldmatrix.sync.aligned.m8n8.x4.trans.shared.b16 {%0,%1,%2,%3}, [%4];"
                 : "=r"(r[0]), "=r"(r[1]), "=r"(r[2]), "=r"(r[3]) : "r"(addr));
}
__device__ __forceinline__ void mma_f16(float* c, const uint32_t* a, uint32_t b0, uint32_t b1) {
    asm volatile(
        "mma.sync.aligned.m16n8k16.row.col.f32.f16.f16.f32 "
        "{%0,%1,%2,%3}, {%4,%5,%6,%7}, {%8,%9}, {%0,%1,%2,%3};"
        : "+f"(c[0]), "+f"(c[1]), "+f"(c[2]), "+f"(c[3])
        : "r"(a[0]), "r"(a[1]), "r"(a[2]), "r"(a[3]), "r"(b0), "r"(b1));
}
__device__ __forceinline__ void cp_async16(uint32_t saddr, const void* gptr) {
    asm volatile("cp.async.cg.shared.global [%0], [%1], 16;" :: "r"(saddr), "l"(gptr));
}
#define CP_COMMIT()  asm volatile("cp.async.commit_group;" ::: "memory")
#define CP_WAIT(n)   asm volatile("cp.async.wait_group %0;" :: "n"(n) : "memory")

// XOR swizzle inside 128B rows: element chunk c (16B) of row r
#define SWZ(r, c) ((uint32_t)(r)*128u + ((((uint32_t)(c)) ^ ((uint32_t)(r) & 7u)) << 4))

// Fast exp2 on FMA pipe. t <= 0 expected.
__device__ __forceinline__ float fexp2(float t) {
    t = fmaxf(t, -126.0f);
    float kf = rintf(t);
    float f = t - kf;
    float p = 0.0013333558f;
    p = fmaf(p, f, 0.0096181291f);
    p = fmaf(p, f, 0.0555041087f);
    p = fmaf(p, f, 0.2402265069f);
    p = fmaf(p, f, 0.6931471806f);
    p = fmaf(p, f, 1.0f);
    return __int_as_float(__float_as_int(p) + (((int)kf) << 23));
}
__device__ __forceinline__ uint32_t pack_f16(__half a, __half b) {
    return ((uint32_t)__half_as_ushort(b) << 16) | (uint32_t)__half_as_ushort(a);
}

// ---------------------------------------------------------------------------
// Conversion kernels
// ---------------------------------------------------------------------------
__global__ __launch_bounds__(256)
void split_kernel(const float* __restrict__ x, __half* __restrict__ xh,
                  __half* __restrict__ xl)
{
    int i = (blockIdx.x * 256 + threadIdx.x) * 4;
    float4 v = *reinterpret_cast<const float4*>(x + i);
    float a[4] = {v.x, v.y, v.z, v.w};
    #pragma unroll
    for (int j = 0; j < 4; j++) {
        __half h = __float2half_rn(a[j]);
        xh[i + j] = h;
        xl[i + j] = __float2half_rn(a[j] - __half2float(h));
    }
}

// W[K,N] fp32 -> WT single fp16 [N,K]
__global__ __launch_bounds__(256)
void tconv_kernel(const float* __restrict__ W, __half* __restrict__ WT, int K, int N)
{
    __shared__ float t[32][33];
    const int k0 = blockIdx.y * 32, n0 = blockIdx.x * 32;
    const int tx = threadIdx.x & 31, ty = threadIdx.x >> 5;
    #pragma unroll
    for (int i = 0; i < 4; i++)
        t[ty + i * 8][tx] = W[(size_t)(k0 + ty + i * 8) * N + n0 + tx];
    __syncthreads();
    #pragma unroll
    for (int i = 0; i < 4; i++) {
        int n = ty + i * 8;
        WT[(size_t)(n0 + n) * K + k0 + tx] = __float2half_rn(t[tx][n]);
    }
}

// ---------------------------------------------------------------------------
// mma.sync GEMM: D = (Ah[+Al])[M,K] @ B[N,K]^T + bias.
// BM=BN=128, BK=64 (128B rows, XOR swizzle -> conflict-free ldmatrix).
// 8 warps (2x4), warp tile 64x32, 2 CTAs/SM, cp.async double buffer.
// LO template flag (dead-code eliminated): LO=true full A hi+lo split,
// LO=false hi-only (outputs / inputs already carry fp16-class error).
// ---------------------------------------------------------------------------
#define TILE_B  16384           // 128 rows * 128B
#define STAGE_B 49152           // 3 tiles (Ah, Al, B)

template<int EPI, bool LO>
__global__ __launch_bounds__(256, 2)
void mma_gemm(const __half* __restrict__ Ah, const __half* __restrict__ Al,
              const __half* __restrict__ Bs,
              const float* __restrict__ bias, float* __restrict__ C,
              int N, int K, int bn0)
{
    extern __shared__ char dsm[];
    const uint32_t sb = smem_to_u32(dsm);

    const int tid = threadIdx.x;
    const int wid = tid >> 5;
    const int lane = tid & 31;
    const int bm = blockIdx.y;
    const int bn = blockIdx.x + bn0;
    const int wm = wid & 1;
    const int wn = wid >> 1;

    const __half* gsrc[3];
    gsrc[0] = Ah + (size_t)bm * 128 * K;
    gsrc[1] = Al + (size_t)bm * 128 * K;
    gsrc[2] = Bs + (size_t)bn * 128 * K;

    auto load_stage = [&](int stage, int k0) {
        uint32_t sdst = sb + stage * STAGE_B;
        #pragma unroll
        for (int op = 0; op < 3; op++) {
            if (op == 1 && !LO) continue;
            const __half* g = gsrc[op];
            #pragma unroll
            for (int i = 0; i < 4; i++) {
                int ch = tid + i * 256;
                int r = ch >> 3, c = ch & 7;
                cp_async16(sdst + op * TILE_B + SWZ(r, c),
                           g + (size_t)r * K + k0 + c * 8);
            }
        }
    };

    float acc[4][4][4];
    #pragma unroll
    for (int mt = 0; mt < 4; mt++)
        #pragma unroll
        for (int nt = 0; nt < 4; nt++)
            #pragma unroll
            for (int r = 0; r < 4; r++) acc[mt][nt][r] = 0.0f;

    const int NCH = K >> 6;    // K/64

    load_stage(0, 0);
    CP_COMMIT();

    const int bg = lane >> 3;

    for (int c = 0; c < NCH; c++) {
        const int stage = c & 1;
        if (c + 1 < NCH) {
            load_stage((c + 1) & 1, (c + 1) * 64);
            CP_COMMIT();
            CP_WAIT(1);
        } else {
            CP_WAIT(0);
        }
        __syncthreads();

        const uint32_t sA_h = sb + stage * STAGE_B + 0 * TILE_B;
        const uint32_t sA_l = sb + stage * STAGE_B + 1 * TILE_B;
        const uint32_t sB   = sb + stage * STAGE_B + 2 * TILE_B;

        #pragma unroll
        for (int ks = 0; ks < 4; ks++) {
            uint32_t bf[2][4];
            #pragma unroll
            for (int nt2 = 0; nt2 < 2; nt2++) {
                int row = wn * 32 + nt2 * 16 + (lane & 7) + ((bg >> 1) << 3);
                ldsm_x4(bf[nt2], sB + SWZ(row, ks * 2 + (bg & 1)));
            }
            #pragma unroll
            for (int mt = 0; mt < 4; mt++) {
                uint32_t ahf[4];
                int row = wm * 64 + mt * 16 + (lane & 15);
                int cc = ks * 2 + (lane >> 4);
                ldsm_x4(ahf, sA_h + SWZ(row, cc));
                #pragma unroll
                for (int nt = 0; nt < 4; nt++)
                    mma_f16(acc[mt][nt], ahf, bf[nt >> 1][(nt & 1) * 2], bf[nt >> 1][(nt & 1) * 2 + 1]);
                if (LO) {
                    uint32_t alf[4];
                    ldsm_x4(alf, sA_l + SWZ(row, cc));
                    #pragma unroll
                    for (int nt = 0; nt < 4; nt++)
                        mma_f16(acc[mt][nt], alf, bf[nt >> 1][(nt & 1) * 2], bf[nt >> 1][(nt & 1) * 2 + 1]);
                }
            }
        }
        __syncthreads();
    }

    // Epilogue: pair (r, r+1) = same row, adjacent cols -> wide stores
    #pragma unroll
    for (int mt = 0; mt < 4; mt++) {
        #pragma unroll
        for (int nt = 0; nt < 4; nt++) {
            #pragma unroll
            for (int rp = 0; rp < 2; rp++) {
                int m = bm * 128 + wm * 64 + mt * 16 + (lane >> 2) + rp * 8;
                int n = bn * 128 + wn * 32 + nt * 8 + (lane & 3) * 2;   // even
                float v0 = acc[mt][nt][rp * 2 + 0] + __ldg(&bias[n]);
                float v1 = acc[mt][nt][rp * 2 + 1] + __ldg(&bias[n + 1]);
                if (EPI == 0) {
                    int part = n >> 10;
                    int b = m >> 11;
                    int s = m & 2047;
                    int col = n & 1023;
                    int hh = col >> 6;
                    int d = col & 63;                      // even
                    size_t idx = (((size_t)(b * 16 + hh) * 2048) + s) * 64 + d;
                    if (part == 0) {
                        v0 *= 0.125f * LOG2E;
                        v1 *= 0.125f * LOG2E;
                        __half h0 = __float2half_rn(v0);
                        __half h1 = __float2half_rn(v1);
                        *reinterpret_cast<uint32_t*>(&g_qh[idx]) = pack_f16(h0, h1);
                        *reinterpret_cast<uint32_t*>(&g_ql[idx]) = pack_f16(
                            __float2half_rn(v0 - __half2float(h0)),
                            __float2half_rn(v1 - __half2float(h1)));
                    } else if (part == 1) {
                        __half2 hp = __floats2half2_rn(v0, v1);
                        *reinterpret_cast<__half2*>(&g_k16[idx]) = hp;
                    } else {
                        __half2 hp = __floats2half2_rn(v0, v1);
                        *reinterpret_cast<__half2*>(&g_v16[idx]) = hp;
                    }
                } else {
                    float2 o = make_float2(v0, v1);
                    *reinterpret_cast<float2*>(&C[(size_t)m * N + n]) = o;
                }
            }
        }
    }
}

// ---------------------------------------------------------------------------
// Tensor-core flash attention: Q fp16-split x K single; P single fp16 x V single.
// Bq=128, Bk=64, 8 warps (warp = 16 q-rows), 2 CTAs/SM.
// Epilogue emits single-fp16 attn (proj tolerates fp16-class input error).
// ---------------------------------------------------------------------------
__global__ __launch_bounds__(256, 2)
void flash_mma()
{
    extern __shared__ char fsm[];
    const uint32_t sb = smem_to_u32(fsm);
    const uint32_t sQh = sb, sQl = sb + 16384;

    const int tid = threadIdx.x;
    const int lane = tid & 31;
    const int wid = tid >> 5;
    const int qt = 15 - blockIdx.x;       // heavy tiles first
    const int bh = blockIdx.y;

    const size_t qoff = ((size_t)bh * SS + qt * 128) * HD;

    auto load_Q = [&]() {
        #pragma unroll
        for (int i = 0; i < 4; i++) {
            int ch = tid + i * 256;
            int r = ch >> 3, c = ch & 7;
            cp_async16(sQh + SWZ(r, c), g_qh + qoff + (size_t)r * 64 + c * 8);
            cp_async16(sQl + SWZ(r, c), g_ql + qoff + (size_t)r * 64 + c * 8);
        }
    };
    auto load_KV = [&](int stage, int kt) {
        uint32_t sbase = sb + 32768 + stage * 16384;
        size_t off = ((size_t)bh * SS + kt * 64) * HD;
        const __half* srcs[2] = { g_k16 + off, g_v16 + off };
        #pragma unroll
        for (int b = 0; b < 2; b++)
            #pragma unroll
            for (int i = 0; i < 2; i++) {
                int ch = tid + i * 256;
                int r = ch >> 3, c = ch & 7;
                cp_async16(sbase + b * 8192 + SWZ(r, c), srcs[b] + (size_t)r * 64 + c * 8);
            }
    };

    const int nkt = 2 * qt + 2;

    load_Q();
    load_KV(0, 0);
    CP_COMMIT();

    uint32_t qh[4][4], ql[4][4];
    float oacc[8][4];
    #pragma unroll
    for (int nt = 0; nt < 8; nt++)
        #pragma unroll
        for (int j = 0; j < 4; j++) oacc[nt][j] = 0.0f;
    float m_s[2] = {-1e30f, -1e30f};
    float l_s[2] = {0.0f, 0.0f};

    for (int kt = 0; kt < nkt; kt++) {
        const int stage = kt & 1;
        if (kt + 1 < nkt) {
            load_KV((kt + 1) & 1, kt + 1);
            CP_COMMIT();
            CP_WAIT(1);
        } else {
            CP_WAIT(0);
        }
        __syncthreads();

        if (kt == 0) {
            #pragma unroll
            for (int t = 0; t < 4; t++) {
                int row = wid * 16 + (lane & 15);
                int c = t * 2 + (lane >> 4);
                ldsm_x4(qh[t], sQh + SWZ(row, c));
                ldsm_x4(ql[t], sQl + SWZ(row, c));
            }
        }

        const uint32_t stK = sb + 32768 + stage * 16384;
        const uint32_t stV = stK + 8192;

        float sacc[8][4];
        #pragma unroll
        for (int nt = 0; nt < 8; nt++)
            #pragma unroll
            for (int j = 0; j < 4; j++) sacc[nt][j] = 0.0f;

        // ---- S = (Qh+Ql) K^T ----
        #pragma unroll
        for (int t = 0; t < 4; t++) {
            uint32_t k4[4][4];
            const int g = lane >> 3;
            #pragma unroll
            for (int p = 0; p < 4; p++) {
                int row = p * 16 + (lane & 7) + ((g >> 1) << 3);
                int c = t * 2 + (g & 1);
                ldsm_x4(k4[p], stK + SWZ(row, c));
            }
            #pragma unroll
            for (int p = 0; p < 4; p++) {
                mma_f16(sacc[2*p],   qh[t], k4[p][0], k4[p][1]);
                mma_f16(sacc[2*p+1], qh[t], k4[p][2], k4[p][3]);
            }
            #pragma unroll
            for (int p = 0; p < 4; p++) {
                mma_f16(sacc[2*p],   ql[t], k4[p][0], k4[p][1]);
                mma_f16(sacc[2*p+1], ql[t], k4[p][2], k4[p][3]);
            }
        }

        if (kt >= 2 * qt) {
            int r0 = qt * 128 + wid * 16 + (lane >> 2);
            #pragma unroll
            for (int nt = 0; nt < 8; nt++)
                #pragma unroll
                for (int j = 0; j < 4; j++) {
                    int row = r0 + (j >> 1) * 8;
                    int col = kt * 64 + nt * 8 + (lane & 3) * 2 + (j & 1);
                    if (col > row) sacc[nt][j] = -1e30f;
                }
        }

        float rmax[2] = {-1e30f, -1e30f};
        #pragma unroll
        for (int nt = 0; nt < 8; nt++) {
            rmax[0] = fmaxf(rmax[0], fmaxf(sacc[nt][0], sacc[nt][1]));
            rmax[1] = fmaxf(rmax[1], fmaxf(sacc[nt][2], sacc[nt][3]));
        }
        #pragma unroll
        for (int h = 0; h < 2; h++) {
            rmax[h] = fmaxf(rmax[h], __shfl_xor_sync(0xffffffffu, rmax[h], 1));
            rmax[h] = fmaxf(rmax[h], __shfl_xor_sync(0xffffffffu, rmax[h], 2));
        }
        float corr[2];
        #pragma unroll
        for (int h = 0; h < 2; h++) {
            float mnew = fmaxf(m_s[h], rmax[h]);
            corr[h] = fexp2(m_s[h] - mnew);
            m_s[h] = mnew;
        }

        // P single fp16
        uint32_t phpk[8][2];
        float rsum[2] = {0.0f, 0.0f};
        #pragma unroll
        for (int nt = 0; nt < 8; nt++) {
            #pragma unroll
            for (int h = 0; h < 2; h++) {
                float p0 = fexp2(sacc[nt][2*h]   - m_s[h]);
                float p1 = fexp2(sacc[nt][2*h+1] - m_s[h]);
                rsum[h] += p0 + p1;
                __half2 hp = __floats2half2_rn(p0, p1);
                phpk[nt][h] = *reinterpret_cast<uint32_t*>(&hp);
            }
        }
        #pragma unroll
        for (int h = 0; h < 2; h++) {
            rsum[h] += __shfl_xor_sync(0xffffffffu, rsum[h], 1);
            rsum[h] += __shfl_xor_sync(0xffffffffu, rsum[h], 2);
            l_s[h] = l_s[h] * corr[h] + rsum[h];
        }
        #pragma unroll
        for (int nt = 0; nt < 8; nt++) {
            oacc[nt][0] *= corr[0];
            oacc[nt][1] *= corr[0];
            oacc[nt][2] *= corr[1];
            oacc[nt][3] *= corr[1];
        }

        // ---- O += P V ----
        #pragma unroll
        for (int t = 0; t < 4; t++) {
            uint32_t pa[4] = { phpk[2*t][0], phpk[2*t][1], phpk[2*t+1][0], phpk[2*t+1][1] };
            uint32_t v4[4][4];
            #pragma unroll
            for (int p = 0; p < 4; p++) {
                int row = t * 16 + (lane & 15);
                int c = 2 * p + (lane >> 4);
                ldsm_x4_t(v4[p], stV + SWZ(row, c));
            }
            #pragma unroll
            for (int p = 0; p < 4; p++) {
                mma_f16(oacc[2*p],   pa, v4[p][0], v4[p][1]);
                mma_f16(oacc[2*p+1], pa, v4[p][2], v4[p][3]);
            }
        }
        __syncthreads();
    }

    const int b = bh >> 4;
    const int head = bh & 15;
    float inv[2] = {1.0f / l_s[0], 1.0f / l_s[1]};
    #pragma unroll
    for (int h = 0; h < 2; h++) {
        int srow = qt * 128 + wid * 16 + (lane >> 2) + h * 8;
        size_t base = ((size_t)(b * SS + srow)) * DD + head * 64 + (lane & 3) * 2;
        #pragma unroll
        for (int nt = 0; nt < 8; nt++) {
            __half2 hp = __floats2half2_rn(oacc[nt][2*h] * inv[h],
                                           oacc[nt][2*h+1] * inv[h]);
            *reinterpret_cast<__half2*>(g_a16 + base + nt * 8) = hp;
        }
    }
}

// ---------------------------------------------------------------------------
extern "C" void kernel_launch(void* const* d_in, const int* in_sizes, int n_in,
                              void* d_out, int out_size)
{
    (void)in_sizes; (void)n_in; (void)out_size;
    const float* x   = (const float*)d_in[0];
    const float* w1  = (const float*)d_in[1];
    const float* b1  = (const float*)d_in[2];
    const float* w2  = (const float*)d_in[3];
    const float* b2  = (const float*)d_in[4];
    float* out = (float*)d_out;

    const int SMEM_DYN = 2 * STAGE_B;          // 98304
    const int SMEM_FL  = 65536;                // 64KB
    cudaFuncSetAttribute((const void*)mma_gemm<0, true>,  cudaFuncAttributeMaxDynamicSharedMemorySize, SMEM_DYN);
    cudaFuncSetAttribute((const void*)mma_gemm<0, false>, cudaFuncAttributeMaxDynamicSharedMemorySize, SMEM_DYN);
    cudaFuncSetAttribute((const void*)mma_gemm<1, false>, cudaFuncAttributeMaxDynamicSharedMemorySize, SMEM_DYN);
    cudaFuncSetAttribute((const void*)flash_mma, cudaFuncAttributeMaxDynamicSharedMemorySize, SMEM_FL);

    void *p_xh, *p_xl, *p_w1t, *p_w2t, *p_a16;
    cudaGetSymbolAddress(&p_xh, g_xh);   cudaGetSymbolAddress(&p_xl, g_xl);
    cudaGetSymbolAddress(&p_w1t, g_w1t); cudaGetSymbolAddress(&p_w2t, g_w2t);
    cudaGetSymbolAddress(&p_a16, g_a16);

    split_kernel<<<MROWS * DD / 1024, 256>>>(x, (__half*)p_xh, (__half*)p_xl);
    tconv_kernel<<<dim3(3 * DD / 32, DD / 32), 256>>>(w1, (__half*)p_w1t, DD, 3 * DD);
    tconv_kernel<<<dim3(DD / 32, DD / 32), 256>>>(w2, (__half*)p_w2t, DD, DD);

    // Q columns: full X split (grid 8 x 32)
    mma_gemm<0, true><<<dim3(8, MROWS / 128), 256, SMEM_DYN>>>(
        (const __half*)p_xh, (const __half*)p_xl, (const __half*)p_w1t,
        b1, nullptr, 3 * DD, DD, 0);
    // K/V columns: hi-only X (grid 16 x 32)
    mma_gemm<0, false><<<dim3(16, MROWS / 128), 256, SMEM_DYN>>>(
        (const __half*)p_xh, (const __half*)p_xl, (const __half*)p_w1t,
        b1, nullptr, 3 * DD, DD, 8);

    flash_mma<<<dim3(SS / 128, BH), 256, SMEM_FL>>>();

    // Projection: single-fp16 attn (error within budget), half the MMAs
    mma_gemm<1, false><<<dim3(DD / 128, MROWS / 128), 256, SMEM_DYN>>>(
        (const __half*)p_a16, (const __half*)p_a16, (const __half*)p_w2t,
        b2, out, DD, DD, 0);
}

// round 16
// speedup vs baseline: 1.9872x; 1.2429x over previous
#include <cuda_runtime.h>
#include <cuda_fp16.h>
#include <cstdint>
#include <math.h>

// Problem constants
#define BB 2
#define SS 2048
#define DD 1024
#define HH 16
#define HD 64
#define BH (BB*HH)          // 32
#define MROWS (BB*SS)       // 4096
#define LOG2E 1.4426950408889634f

// ---------------------------------------------------------------------------
// Scratch (static device globals: allocation-free)
// ---------------------------------------------------------------------------
__device__ __half g_q16[BH*SS*HD];    // Q single fp16 (exp2-domain scaled)
__device__ __half g_k16[BH*SS*HD];    // K single fp16
__device__ __half g_v16[BH*SS*HD];    // V single fp16
__device__ __half g_x16[MROWS*DD];    // X single fp16
__device__ __half g_w1t[3*DD*DD];     // W1^T single fp16 [3072,1024]
__device__ __half g_w2t[DD*DD];       // W2^T single fp16 [1024,1024]
__device__ __half g_a16[MROWS*DD];    // attn out single fp16

// ---------------------------------------------------------------------------
// PTX helpers (sm_80-portable: mma.sync / ldmatrix / cp.async)
// ---------------------------------------------------------------------------
__device__ __forceinline__ uint32_t smem_to_u32(const void* p) {
    uint32_t a;
    asm("{ .reg .u64 t; cvta.to.shared.u64 t, %1; cvt.u32.u64 %0, t; }"
        : "=r"(a) : "l"(p));
    return a;
}
__device__ __forceinline__ void ldsm_x4(uint32_t* r, uint32_t addr) {
    asm volatile("ldmatrix.sync.aligned.m8n8.x4.shared.b16 {%0,%1,%2,%3}, [%4];"
                 : "=r"(r[0]), "=r"(r[1]), "=r"(r[2]), "=r"(r[3]) : "r"(addr));
}
__device__ __forceinline__ void ldsm_x4_t(uint32_t* r, uint32_t addr) {
    asm volatile("ldmatrix.sync.aligned.m8n8.x4.trans.shared.b16 {%0,%1,%2,%3}, [%4];"
                 : "=r"(r[0]), "=r"(r[1]), "=r"(r[2]), "=r"(r[3]) : "r"(addr));
}
__device__ __forceinline__ void mma_f16(float* c, const uint32_t* a, uint32_t b0, uint32_t b1) {
    asm volatile(
        "mma.sync.aligned.m16n8k16.row.col.f32.f16.f16.f32 "
        "{%0,%1,%2,%3}, {%4,%5,%6,%7}, {%8,%9}, {%0,%1,%2,%3};"
        : "+f"(c[0]), "+f"(c[1]), "+f"(c[2]), "+f"(c[3])
        : "r"(a[0]), "r"(a[1]), "r"(a[2]), "r"(a[3]), "r"(b0), "r"(b1));
}
__device__ __forceinline__ void cp_async16(uint32_t saddr, const void* gptr) {
    asm volatile("cp.async.cg.shared.global [%0], [%1], 16;" :: "r"(saddr), "l"(gptr));
}
#define CP_COMMIT()  asm volatile("cp.async.commit_group;" ::: "memory")
#define CP_WAIT(n)   asm volatile("cp.async.wait_group %0;" :: "n"(n) : "memory")

// XOR swizzle inside 128B rows: element chunk c (16B) of row r
#define SWZ(r, c) ((uint32_t)(r)*128u + ((((uint32_t)(c)) ^ ((uint32_t)(r) & 7u)) << 4))

// Fast exp2 on FMA pipe. t <= 0 expected.
__device__ __forceinline__ float fexp2(float t) {
    t = fmaxf(t, -126.0f);
    float kf = rintf(t);
    float f = t - kf;
    float p = 0.0013333558f;
    p = fmaf(p, f, 0.0096181291f);
    p = fmaf(p, f, 0.0555041087f);
    p = fmaf(p, f, 0.2402265069f);
    p = fmaf(p, f, 0.6931471806f);
    p = fmaf(p, f, 1.0f);
    return __int_as_float(__float_as_int(p) + (((int)kf) << 23));
}

// ---------------------------------------------------------------------------
// Conversion kernels
// ---------------------------------------------------------------------------
__global__ __launch_bounds__(256)
void conv_kernel(const float* __restrict__ x, __half* __restrict__ xh)
{
    int i = (blockIdx.x * 256 + threadIdx.x) * 4;
    float4 v = *reinterpret_cast<const float4*>(x + i);
    __half2 a = __floats2half2_rn(v.x, v.y);
    __half2 b = __floats2half2_rn(v.z, v.w);
    *reinterpret_cast<__half2*>(xh + i)     = a;
    *reinterpret_cast<__half2*>(xh + i + 2) = b;
}

// W[K,N] fp32 -> WT single fp16 [N,K]
__global__ __launch_bounds__(256)
void tconv_kernel(const float* __restrict__ W, __half* __restrict__ WT, int K, int N)
{
    __shared__ float t[32][33];
    const int k0 = blockIdx.y * 32, n0 = blockIdx.x * 32;
    const int tx = threadIdx.x & 31, ty = threadIdx.x >> 5;
    #pragma unroll
    for (int i = 0; i < 4; i++)
        t[ty + i * 8][tx] = W[(size_t)(k0 + ty + i * 8) * N + n0 + tx];
    __syncthreads();
    #pragma unroll
    for (int i = 0; i < 4; i++) {
        int n = ty + i * 8;
        WT[(size_t)(n0 + n) * K + k0 + tx] = __float2half_rn(t[tx][n]);
    }
}

// ---------------------------------------------------------------------------
// mma.sync GEMM: D = A[M,K] @ B[N,K]^T + bias  (single fp16 operands).
// BM=BN=128, BK=64 (128B rows, XOR swizzle -> conflict-free ldmatrix).
// 8 warps (2x4), warp tile 64x32, 2 CTAs/SM, cp.async double buffer.
// EPI=0: Q (scaled, exp2-domain) / K / V single-fp16 head-major scatter.
// EPI=1: fp32 C.
// ---------------------------------------------------------------------------
#define TILE_B  16384           // 128 rows * 128B
#define STAGE_B 32768           // 2 tiles (A, B)

template<int EPI>
__global__ __launch_bounds__(256, 2)
void mma_gemm(const __half* __restrict__ As, const __half* __restrict__ Bs,
              const float* __restrict__ bias, float* __restrict__ C,
              int N, int K)
{
    extern __shared__ char dsm[];
    const uint32_t sb = smem_to_u32(dsm);

    const int tid = threadIdx.x;
    const int wid = tid >> 5;
    const int lane = tid & 31;
    const int bm = blockIdx.y;
    const int bn = blockIdx.x;
    const int wm = wid & 1;
    const int wn = wid >> 1;

    const __half* gA = As + (size_t)bm * 128 * K;
    const __half* gB = Bs + (size_t)bn * 128 * K;

    auto load_stage = [&](int stage, int k0) {
        uint32_t sdst = sb + stage * STAGE_B;
        #pragma unroll
        for (int i = 0; i < 4; i++) {
            int ch = tid + i * 256;
            int r = ch >> 3, c = ch & 7;
            cp_async16(sdst + SWZ(r, c), gA + (size_t)r * K + k0 + c * 8);
            cp_async16(sdst + TILE_B + SWZ(r, c), gB + (size_t)r * K + k0 + c * 8);
        }
    };

    float acc[4][4][4];
    #pragma unroll
    for (int mt = 0; mt < 4; mt++)
        #pragma unroll
        for (int nt = 0; nt < 4; nt++)
            #pragma unroll
            for (int r = 0; r < 4; r++) acc[mt][nt][r] = 0.0f;

    const int NCH = K >> 6;    // K/64

    load_stage(0, 0);
    CP_COMMIT();

    const int bg = lane >> 3;

    for (int c = 0; c < NCH; c++) {
        const int stage = c & 1;
        if (c + 1 < NCH) {
            load_stage((c + 1) & 1, (c + 1) * 64);
            CP_COMMIT();
            CP_WAIT(1);
        } else {
            CP_WAIT(0);
        }
        __syncthreads();

        const uint32_t sA = sb + stage * STAGE_B;
        const uint32_t sB = sA + TILE_B;

        #pragma unroll
        for (int ks = 0; ks < 4; ks++) {
            uint32_t bf[2][4];
            #pragma unroll
            for (int nt2 = 0; nt2 < 2; nt2++) {
                int row = wn * 32 + nt2 * 16 + (lane & 7) + ((bg >> 1) << 3);
                ldsm_x4(bf[nt2], sB + SWZ(row, ks * 2 + (bg & 1)));
            }
            #pragma unroll
            for (int mt = 0; mt < 4; mt++) {
                uint32_t af[4];
                int row = wm * 64 + mt * 16 + (lane & 15);
                int cc = ks * 2 + (lane >> 4);
                ldsm_x4(af, sA + SWZ(row, cc));
                #pragma unroll
                for (int nt = 0; nt < 4; nt++)
                    mma_f16(acc[mt][nt], af, bf[nt >> 1][(nt & 1) * 2], bf[nt >> 1][(nt & 1) * 2 + 1]);
            }
        }
        __syncthreads();
    }

    // Epilogue: pair (r, r+1) = same row, adjacent cols -> wide stores
    #pragma unroll
    for (int mt = 0; mt < 4; mt++) {
        #pragma unroll
        for (int nt = 0; nt < 4; nt++) {
            #pragma unroll
            for (int rp = 0; rp < 2; rp++) {
                int m = bm * 128 + wm * 64 + mt * 16 + (lane >> 2) + rp * 8;
                int n = bn * 128 + wn * 32 + nt * 8 + (lane & 3) * 2;   // even
                float v0 = acc[mt][nt][rp * 2 + 0] + __ldg(&bias[n]);
                float v1 = acc[mt][nt][rp * 2 + 1] + __ldg(&bias[n + 1]);
                if (EPI == 0) {
                    int part = n >> 10;
                    int b = m >> 11;
                    int s = m & 2047;
                    int col = n & 1023;
                    int hh = col >> 6;
                    int d = col & 63;                      // even
                    size_t idx = (((size_t)(b * 16 + hh) * 2048) + s) * 64 + d;
                    __half* dst;
                    if (part == 0) {
                        v0 *= 0.125f * LOG2E;              // scale + exp2-domain fold
                        v1 *= 0.125f * LOG2E;
                        dst = g_q16;
                    } else if (part == 1) {
                        dst = g_k16;
                    } else {
                        dst = g_v16;
                    }
                    __half2 hp = __floats2half2_rn(v0, v1);
                    *reinterpret_cast<__half2*>(&dst[idx]) = hp;
                } else {
                    float2 o = make_float2(v0, v1);
                    *reinterpret_cast<float2*>(&C[(size_t)m * N + n]) = o;
                }
            }
        }
    }
}

// ---------------------------------------------------------------------------
// Tensor-core flash attention: all single fp16 (Q, K, P, V).
// Bq=128, Bk=64, 8 warps (warp = 16 q-rows), 2 CTAs/SM.
// smem: Q 16KB + 2 stages x (K,V) 16KB = 48KB per CTA.
// ---------------------------------------------------------------------------
__global__ __launch_bounds__(256, 2)
void flash_mma()
{
    extern __shared__ char fsm[];
    const uint32_t sb = smem_to_u32(fsm);
    const uint32_t sQ = sb;

    const int tid = threadIdx.x;
    const int lane = tid & 31;
    const int wid = tid >> 5;
    const int qt = 15 - blockIdx.x;       // heavy tiles first
    const int bh = blockIdx.y;

    const size_t qoff = ((size_t)bh * SS + qt * 128) * HD;

    auto load_Q = [&]() {
        #pragma unroll
        for (int i = 0; i < 4; i++) {
            int ch = tid + i * 256;
            int r = ch >> 3, c = ch & 7;
            cp_async16(sQ + SWZ(r, c), g_q16 + qoff + (size_t)r * 64 + c * 8);
        }
    };
    auto load_KV = [&](int stage, int kt) {
        uint32_t sbase = sb + 16384 + stage * 16384;
        size_t off = ((size_t)bh * SS + kt * 64) * HD;
        const __half* srcs[2] = { g_k16 + off, g_v16 + off };
        #pragma unroll
        for (int b = 0; b < 2; b++)
            #pragma unroll
            for (int i = 0; i < 2; i++) {
                int ch = tid + i * 256;
                int r = ch >> 3, c = ch & 7;
                cp_async16(sbase + b * 8192 + SWZ(r, c), srcs[b] + (size_t)r * 64 + c * 8);
            }
    };

    const int nkt = 2 * qt + 2;

    load_Q();
    load_KV(0, 0);
    CP_COMMIT();

    uint32_t qf[4][4];
    float oacc[8][4];
    #pragma unroll
    for (int nt = 0; nt < 8; nt++)
        #pragma unroll
        for (int j = 0; j < 4; j++) oacc[nt][j] = 0.0f;
    float m_s[2] = {-1e30f, -1e30f};
    float l_s[2] = {0.0f, 0.0f};

    for (int kt = 0; kt < nkt; kt++) {
        const int stage = kt & 1;
        if (kt + 1 < nkt) {
            load_KV((kt + 1) & 1, kt + 1);
            CP_COMMIT();
            CP_WAIT(1);
        } else {
            CP_WAIT(0);
        }
        __syncthreads();

        if (kt == 0) {
            #pragma unroll
            for (int t = 0; t < 4; t++) {
                int row = wid * 16 + (lane & 15);
                int c = t * 2 + (lane >> 4);
                ldsm_x4(qf[t], sQ + SWZ(row, c));
            }
        }

        const uint32_t stK = sb + 16384 + stage * 16384;
        const uint32_t stV = stK + 8192;

        float sacc[8][4];
        #pragma unroll
        for (int nt = 0; nt < 8; nt++)
            #pragma unroll
            for (int j = 0; j < 4; j++) sacc[nt][j] = 0.0f;

        // ---- S = Q K^T (single fp16) ----
        #pragma unroll
        for (int t = 0; t < 4; t++) {
            uint32_t k4[4][4];
            const int g = lane >> 3;
            #pragma unroll
            for (int p = 0; p < 4; p++) {
                int row = p * 16 + (lane & 7) + ((g >> 1) << 3);
                int c = t * 2 + (g & 1);
                ldsm_x4(k4[p], stK + SWZ(row, c));
            }
            #pragma unroll
            for (int p = 0; p < 4; p++) {
                mma_f16(sacc[2*p],   qf[t], k4[p][0], k4[p][1]);
                mma_f16(sacc[2*p+1], qf[t], k4[p][2], k4[p][3]);
            }
        }

        if (kt >= 2 * qt) {
            int r0 = qt * 128 + wid * 16 + (lane >> 2);
            #pragma unroll
            for (int nt = 0; nt < 8; nt++)
                #pragma unroll
                for (int j = 0; j < 4; j++) {
                    int row = r0 + (j >> 1) * 8;
                    int col = kt * 64 + nt * 8 + (lane & 3) * 2 + (j & 1);
                    if (col > row) sacc[nt][j] = -1e30f;
                }
        }

        float rmax[2] = {-1e30f, -1e30f};
        #pragma unroll
        for (int nt = 0; nt < 8; nt++) {
            rmax[0] = fmaxf(rmax[0], fmaxf(sacc[nt][0], sacc[nt][1]));
            rmax[1] = fmaxf(rmax[1], fmaxf(sacc[nt][2], sacc[nt][3]));
        }
        #pragma unroll
        for (int h = 0; h < 2; h++) {
            rmax[h] = fmaxf(rmax[h], __shfl_xor_sync(0xffffffffu, rmax[h], 1));
            rmax[h] = fmaxf(rmax[h], __shfl_xor_sync(0xffffffffu, rmax[h], 2));
        }
        float corr[2];
        #pragma unroll
        for (int h = 0; h < 2; h++) {
            float mnew = fmaxf(m_s[h], rmax[h]);
            corr[h] = fexp2(m_s[h] - mnew);
            m_s[h] = mnew;
        }

        // P single fp16
        uint32_t phpk[8][2];
        float rsum[2] = {0.0f, 0.0f};
        #pragma unroll
        for (int nt = 0; nt < 8; nt++) {
            #pragma unroll
            for (int h = 0; h < 2; h++) {
                float p0 = fexp2(sacc[nt][2*h]   - m_s[h]);
                float p1 = fexp2(sacc[nt][2*h+1] - m_s[h]);
                rsum[h] += p0 + p1;
                __half2 hp = __floats2half2_rn(p0, p1);
                phpk[nt][h] = *reinterpret_cast<uint32_t*>(&hp);
            }
        }
        #pragma unroll
        for (int h = 0; h < 2; h++) {
            rsum[h] += __shfl_xor_sync(0xffffffffu, rsum[h], 1);
            rsum[h] += __shfl_xor_sync(0xffffffffu, rsum[h], 2);
            l_s[h] = l_s[h] * corr[h] + rsum[h];
        }
        #pragma unroll
        for (int nt = 0; nt < 8; nt++) {
            oacc[nt][0] *= corr[0];
            oacc[nt][1] *= corr[0];
            oacc[nt][2] *= corr[1];
            oacc[nt][3] *= corr[1];
        }

        // ---- O += P V ----
        #pragma unroll
        for (int t = 0; t < 4; t++) {
            uint32_t pa[4] = { phpk[2*t][0], phpk[2*t][1], phpk[2*t+1][0], phpk[2*t+1][1] };
            uint32_t v4[4][4];
            #pragma unroll
            for (int p = 0; p < 4; p++) {
                int row = t * 16 + (lane & 15);
                int c = 2 * p + (lane >> 4);
                ldsm_x4_t(v4[p], stV + SWZ(row, c));
            }
            #pragma unroll
            for (int p = 0; p < 4; p++) {
                mma_f16(oacc[2*p],   pa, v4[p][0], v4[p][1]);
                mma_f16(oacc[2*p+1], pa, v4[p][2], v4[p][3]);
            }
        }
        __syncthreads();
    }

    const int b = bh >> 4;
    const int head = bh & 15;
    float inv[2] = {1.0f / l_s[0], 1.0f / l_s[1]};
    #pragma unroll
    for (int h = 0; h < 2; h++) {
        int srow = qt * 128 + wid * 16 + (lane >> 2) + h * 8;
        size_t base = ((size_t)(b * SS + srow)) * DD + head * 64 + (lane & 3) * 2;
        #pragma unroll
        for (int nt = 0; nt < 8; nt++) {
            __half2 hp = __floats2half2_rn(oacc[nt][2*h] * inv[h],
                                           oacc[nt][2*h+1] * inv[h]);
            *reinterpret_cast<__half2*>(g_a16 + base + nt * 8) = hp;
        }
    }
}

// ---------------------------------------------------------------------------
extern "C" void kernel_launch(void* const* d_in, const int* in_sizes, int n_in,
                              void* d_out, int out_size)
{
    (void)in_sizes; (void)n_in; (void)out_size;
    const float* x   = (const float*)d_in[0];
    const float* w1  = (const float*)d_in[1];
    const float* b1  = (const float*)d_in[2];
    const float* w2  = (const float*)d_in[3];
    const float* b2  = (const float*)d_in[4];
    float* out = (float*)d_out;

    const int SMEM_DYN = 2 * STAGE_B;          // 65536
    const int SMEM_FL  = 49152;                // 48KB
    cudaFuncSetAttribute((const void*)mma_gemm<0>, cudaFuncAttributeMaxDynamicSharedMemorySize, SMEM_DYN);
    cudaFuncSetAttribute((const void*)mma_gemm<1>, cudaFuncAttributeMaxDynamicSharedMemorySize, SMEM_DYN);
    cudaFuncSetAttribute((const void*)flash_mma, cudaFuncAttributeMaxDynamicSharedMemorySize, SMEM_FL);

    void *p_x16, *p_w1t, *p_w2t, *p_a16;
    cudaGetSymbolAddress(&p_x16, g_x16);
    cudaGetSymbolAddress(&p_w1t, g_w1t);
    cudaGetSymbolAddress(&p_w2t, g_w2t);
    cudaGetSymbolAddress(&p_a16, g_a16);

    conv_kernel<<<MROWS * DD / 1024, 256>>>(x, (__half*)p_x16);
    tconv_kernel<<<dim3(3 * DD / 32, DD / 32), 256>>>(w1, (__half*)p_w1t, DD, 3 * DD);
    tconv_kernel<<<dim3(DD / 32, DD / 32), 256>>>(w2, (__half*)p_w2t, DD, DD);

    // QKV: single fp16 everywhere, one uniform launch (grid 24 x 32)
    mma_gemm<0><<<dim3(3 * DD / 128, MROWS / 128), 256, SMEM_DYN>>>(
        (const __half*)p_x16, (const __half*)p_w1t, b1, nullptr, 3 * DD, DD);

    flash_mma<<<dim3(SS / 128, BH), 256, SMEM_FL>>>();

    // Projection: single fp16 attn x single fp16 W2
    mma_gemm<1><<<dim3(DD / 128, MROWS / 128), 256, SMEM_DYN>>>(
        (const __half*)p_a16, (const __half*)p_w2t, b2, out, DD, DD);
}